// round 8
// baseline (speedup 1.0000x reference)
#include <cuda_runtime.h>
#include <cuda_fp16.h>
#include <cstdint>
#include <cstddef>

#define B_    2
#define L_    192
#define H_    512
#define NH_   8
#define ML_   (B_*L_)     // 384 rows (b,l) flattened
#define TROWS_ 383        // distinct position diffs: [-191, 191]
#define SCP_  196         // padded score row (bank-conflict-free 8-lane stores)

// ---------------- scratch (device globals; no allocation allowed) ----------------
static __device__ __align__(16) __half d_Th[4 * TROWS_ * H_];   // 4 pe tables (half; T0 includes b_fus)
static __device__ __align__(16) float  d_kproj[ML_ * H_];
static __device__ __align__(16) float  d_qkA[ML_ * H_];         // qproj + bq + u_bias
static __device__ __align__(16) float  d_u[ML_ * H_];           // qproj + bq + v_bias
static __device__ __align__(16) __half d_vh[ML_ * H_];          // v projection (half)
static __device__ __align__(16) __half d_gh[ML_ * NH_ * H_];    // u_head @ Wr_head (half)
static __device__ __align__(16) float  d_qk[2 * NH_ * L_ * L_]; // per-head (q+u_bias).k
static __device__ __align__(16) float  d_attnout[ML_ * H_];

__device__ __forceinline__ float st_conv(float v, float*)  { return v; }
__device__ __forceinline__ __half st_conv(float v, __half*) { return __float2half(v); }

// Shared tile storage: declared ONCE per kernel, passed by pointer so that
// multiple gemm_tile call sites share a single 17 KB buffer (inlined static
// __shared__ per call site blew past the 48 KB static limit).
struct SmemTiles {
    float As[2][16][68];
    float Bs[2][16][68];
};

// ------- tiled SGEMM: 64x64 tile, BK=16, 4x4 microtile, DOUBLE-BUFFERED smem -------
template<bool TRANSB, bool ATOMIC, typename OT>
__device__ __forceinline__ void gemm_tile(
    SmemTiles* st,
    const float* __restrict__ A, int lda,
    const float* __restrict__ B, int ldb,
    const float* __restrict__ bias,
    OT* __restrict__ C, int ldc,
    int M, int N, int K,
    const float* __restrict__ addA = nullptr,
    float* __restrict__ C2 = nullptr,
    const float* __restrict__ add2 = nullptr)
{
    const int tid = threadIdx.x;
    const int tx = tid & 15, ty = tid >> 4;
    const int m0 = blockIdx.y * 64, n0 = blockIdx.x * 64;
    float acc[4][4];
#pragma unroll
    for (int i = 0; i < 4; ++i)
#pragma unroll
        for (int j = 0; j < 4; ++j) acc[i][j] = 0.f;

    const int lm = tid >> 2;          // 0..63
    const int lk = (tid & 3) * 4;     // 0,4,8,12
    const int bk = tid >> 4;          // 0..15 (NN B)
    const int bn = (tid & 15) * 4;    // 0..60

    {
        float4 av = make_float4(0.f, 0.f, 0.f, 0.f);
        if (m0 + lm < M)
            av = *reinterpret_cast<const float4*>(A + (size_t)(m0 + lm) * lda + lk);
        st->As[0][lk + 0][lm] = av.x; st->As[0][lk + 1][lm] = av.y;
        st->As[0][lk + 2][lm] = av.z; st->As[0][lk + 3][lm] = av.w;
        if (TRANSB) {
            float4 bv = make_float4(0.f, 0.f, 0.f, 0.f);
            if (n0 + lm < N)
                bv = *reinterpret_cast<const float4*>(B + (size_t)(n0 + lm) * ldb + lk);
            st->Bs[0][lk + 0][lm] = bv.x; st->Bs[0][lk + 1][lm] = bv.y;
            st->Bs[0][lk + 2][lm] = bv.z; st->Bs[0][lk + 3][lm] = bv.w;
        } else {
            float4 bv = make_float4(0.f, 0.f, 0.f, 0.f);
            if (n0 + bn < N)
                bv = *reinterpret_cast<const float4*>(B + (size_t)bk * ldb + n0 + bn);
            *reinterpret_cast<float4*>(&st->Bs[0][bk][bn]) = bv;
        }
    }
    __syncthreads();

    int buf = 0;
    for (int k0 = 0; k0 < K; k0 += 16) {
        const bool has_next = (k0 + 16 < K);
        float4 av = make_float4(0.f, 0.f, 0.f, 0.f);
        float4 bv = make_float4(0.f, 0.f, 0.f, 0.f);
        if (has_next) {
            const int kn = k0 + 16;
            if (m0 + lm < M)
                av = *reinterpret_cast<const float4*>(A + (size_t)(m0 + lm) * lda + kn + lk);
            if (TRANSB) {
                if (n0 + lm < N)
                    bv = *reinterpret_cast<const float4*>(B + (size_t)(n0 + lm) * ldb + kn + lk);
            } else {
                if (n0 + bn < N)
                    bv = *reinterpret_cast<const float4*>(B + (size_t)(kn + bk) * ldb + n0 + bn);
            }
        }
#pragma unroll
        for (int kk = 0; kk < 16; ++kk) {
            float a[4], bb[4];
#pragma unroll
            for (int i = 0; i < 4; ++i) a[i] = st->As[buf][kk][ty * 4 + i];
#pragma unroll
            for (int j = 0; j < 4; ++j) bb[j] = st->Bs[buf][kk][tx * 4 + j];
#pragma unroll
            for (int i = 0; i < 4; ++i)
#pragma unroll
                for (int j = 0; j < 4; ++j) acc[i][j] += a[i] * bb[j];
        }
        if (has_next) {
            const int nb = buf ^ 1;
            st->As[nb][lk + 0][lm] = av.x; st->As[nb][lk + 1][lm] = av.y;
            st->As[nb][lk + 2][lm] = av.z; st->As[nb][lk + 3][lm] = av.w;
            if (TRANSB) {
                st->Bs[nb][lk + 0][lm] = bv.x; st->Bs[nb][lk + 1][lm] = bv.y;
                st->Bs[nb][lk + 2][lm] = bv.z; st->Bs[nb][lk + 3][lm] = bv.w;
            } else {
                *reinterpret_cast<float4*>(&st->Bs[nb][bk][bn]) = bv;
            }
        }
        __syncthreads();
        buf ^= 1;
    }

    const int mo = m0 + ty * 4, no = n0 + tx * 4;
#pragma unroll
    for (int i = 0; i < 4; ++i) {
        if (mo + i < M) {
#pragma unroll
            for (int j = 0; j < 4; ++j) {
                if (no + j < N) {
                    float base = acc[i][j];
                    if (bias) base += bias[no + j];
                    if (ATOMIC) {
                        atomicAdd(reinterpret_cast<float*>(&C[(size_t)(mo + i) * ldc + no + j]), base);
                    } else {
                        float v1 = base;
                        if (addA) v1 += addA[no + j];
                        C[(size_t)(mo + i) * ldc + no + j] = st_conv(v1, (OT*)nullptr);
                        if (C2) C2[(size_t)(mo + i) * ldc + no + j] = base + add2[no + j];
                    }
                }
            }
        }
    }
}

// ---------------- stage 1: q/k/v projections ONLY (critical-path prefix) ----------------
__global__ void __launch_bounds__(256) k_proj(
    const float* __restrict__ key, const float* __restrict__ query, const float* __restrict__ value,
    const float* __restrict__ Wk, const float* __restrict__ bk,
    const float* __restrict__ Wq, const float* __restrict__ bq,
    const float* __restrict__ Wv, const float* __restrict__ bv,
    const float* __restrict__ u_bias, const float* __restrict__ v_bias)
{
    __shared__ SmemTiles st;
    const int z = blockIdx.z;
    if (z == 0) {
        gemm_tile<true, false>(&st, key, H_, Wk, H_, bk, d_kproj, H_, ML_, H_, H_);
    } else if (z == 1) {
        // dual write: d_qkA = q@Wq^T + bq + u_bias ; d_u = q@Wq^T + bq + v_bias
        gemm_tile<true, false>(&st, query, H_, Wq, H_, bq, d_qkA, H_, ML_, H_, H_,
                               u_bias, d_u, v_bias);
    } else {
        gemm_tile<true, false>(&st, value, H_, Wv, H_, bv, d_vh, H_, ML_, H_, H_);
    }
}

// ---- stage 2: g + qk GEMMs + pe tables (independent of proj!) + zero d_out, one launch ----
__global__ void __launch_bounds__(256) k_mid(
    const float* __restrict__ Wr,
    const float* __restrict__ pe, const float* __restrict__ W_fus,
    const float* __restrict__ b_fus,
    float* __restrict__ out)
{
    __shared__ SmemTiles st;
    const int z = blockIdx.z;
    if (z < 8) {
        // g[m, z, f] = sum_d u[m, z*64+d] * Wr[z*64+d, f]
        gemm_tile<false, false>(&st, d_u + z * 64, H_, Wr + (size_t)z * 64 * H_, H_, nullptr,
                                d_gh + (size_t)z * H_, NH_ * H_, ML_, H_, 64);
    } else if (z < 24) {
        if (blockIdx.x >= 3 || blockIdx.y >= 3) return;
        const int idx = z - 8;         // b*8 + n
        const int b = idx >> 3, n = idx & 7;
        gemm_tile<true, false>(&st, d_qkA   + (size_t)b * L_ * H_ + n * 64, H_,
                               d_kproj + (size_t)b * L_ * H_ + n * 64, H_, nullptr,
                               d_qk + (size_t)idx * L_ * L_, L_, L_, L_, 64);
    } else if (z < 28) {
        const int t = z - 24;   // table 0..3; b_fus folded into T0
        gemm_tile<true, false>(&st, pe + 321 * H_, H_, W_fus + t * 256, 2 * H_,
                               (t == 0) ? b_fus : nullptr,
                               d_Th + (size_t)t * TROWS_ * H_, H_, TROWS_, H_, 256);
    } else {
        // zero d_out for k_ff's atomic accumulation
        const float4 z4 = make_float4(0.f, 0.f, 0.f, 0.f);
        float4* o4 = reinterpret_cast<float4*>(out);
        const int stride = 48 * 256;
        const int start = (blockIdx.y * 8 + blockIdx.x) * 256 + threadIdx.x;
        for (int i = start; i < (ML_ * H_) / 4; i += stride) o4[i] = z4;
    }
}

__device__ __forceinline__ __half2 shfl_xor_h2(__half2 v, int s) {
    unsigned u = *reinterpret_cast<unsigned*>(&v);
    u = __shfl_xor_sync(0xffffffffu, u, s);
    return *reinterpret_cast<__half2*>(&u);
}

// ------ stage 3: fused rel-scores + softmax + attn@V per (b,q)  [R5 pipelined version] ------
__global__ void __launch_bounds__(256, 3) k_attn(
    const int* __restrict__ pos_s,
    const int* __restrict__ pos_e,
    const int* __restrict__ seq_len)
{
    __shared__ __align__(16) __half g_s[NH_][H_];    // 8 KB
    __shared__ __align__(16) float sc[NH_][SCP_];    // padded: 8-lane stores conflict-free
    __shared__ int ksp[L_], kep[L_];

    const int m = blockIdx.x;          // b*L + q
    const int b = m / L_;
    const int qi = m % L_;
    const int tid = threadIdx.x;
    const int lane = tid & 31;
    const int warp = tid >> 5;

    {
        const uint4* src = reinterpret_cast<const uint4*>(d_gh + (size_t)m * (NH_ * H_));
        uint4* dst = reinterpret_cast<uint4*>(&g_s[0][0]);
        for (int i = tid; i < (NH_ * H_) / 8; i += 256) dst[i] = src[i];
    }
    for (int i = tid; i < NH_ * L_; i += 256) {
        const int n = i / L_, k = i % L_;
        sc[n][k] = d_qk[((size_t)(b * NH_ + n) * L_ + qi) * L_ + k];
    }
    for (int i = tid; i < L_; i += 256) { ksp[i] = pos_s[b * L_ + i]; kep[i] = pos_e[b * L_ + i]; }
    const int psq = pos_s[m], peq = pos_e[m];
    const int slen = seq_len[b];
    __syncthreads();

    const __half2 hz = __float2half2_rn(0.f);
    const __half* __restrict__ T = d_Th;
    const int lane8 = lane << 3;

    // --- software-pipelined score loop: warp w handles keys w, w+8, ... ---
    int o0, o1, o2, o3;
    {
        const int kk0 = warp;
        o0 = ((0 * TROWS_ + psq - ksp[kk0] + 191) << 9);
        o1 = ((1 * TROWS_ + psq - kep[kk0] + 191) << 9);
        o2 = ((2 * TROWS_ + peq - ksp[kk0] + 191) << 9);
        o3 = ((3 * TROWS_ + peq - kep[kk0] + 191) << 9);
    }
    uint4 A0 = *reinterpret_cast<const uint4*>(T + o0 + lane8);
    uint4 A1 = *reinterpret_cast<const uint4*>(T + o1 + lane8);
    uint4 A2 = *reinterpret_cast<const uint4*>(T + o2 + lane8);
    uint4 A3 = *reinterpret_cast<const uint4*>(T + o3 + lane8);

    int kk = warp;
#pragma unroll 1
    for (int t = 0; t < 24; ++t) {
        __half2 acc[NH_];
#pragma unroll
        for (int n = 0; n < NH_; ++n) acc[n] = hz;

        // prefetch second chunk of current key
        uint4 B0 = *reinterpret_cast<const uint4*>(T + o0 + lane8 + 256);
        uint4 B1 = *reinterpret_cast<const uint4*>(T + o1 + lane8 + 256);
        uint4 B2 = *reinterpret_cast<const uint4*>(T + o2 + lane8 + 256);
        uint4 B3 = *reinterpret_cast<const uint4*>(T + o3 + lane8 + 256);

        {
            const __half2* c0 = reinterpret_cast<const __half2*>(&A0);
            const __half2* c1 = reinterpret_cast<const __half2*>(&A1);
            const __half2* c2 = reinterpret_cast<const __half2*>(&A2);
            const __half2* c3 = reinterpret_cast<const __half2*>(&A3);
            __half2 r[4];
#pragma unroll
            for (int j = 0; j < 4; ++j) {
                __half2 s = __hadd2(__hadd2(c0[j], c1[j]), __hadd2(c2[j], c3[j]));
                r[j] = __hmax2(s, hz);   // b_fus folded into T0
            }
#pragma unroll
            for (int n = 0; n < NH_; ++n) {
                uint4 gg = *reinterpret_cast<const uint4*>(&g_s[n][lane8]);
                const __half2* gh = reinterpret_cast<const __half2*>(&gg);
#pragma unroll
                for (int j = 0; j < 4; ++j) acc[n] = __hfma2(gh[j], r[j], acc[n]);
            }
        }

        // prefetch first chunk of NEXT key (covers the reduction + chunk-1 compute)
        if (t < 23) {
            const int kn = kk + 8;
            o0 = ((0 * TROWS_ + psq - ksp[kn] + 191) << 9);
            o1 = ((1 * TROWS_ + psq - kep[kn] + 191) << 9);
            o2 = ((2 * TROWS_ + peq - ksp[kn] + 191) << 9);
            o3 = ((3 * TROWS_ + peq - kep[kn] + 191) << 9);
            A0 = *reinterpret_cast<const uint4*>(T + o0 + lane8);
            A1 = *reinterpret_cast<const uint4*>(T + o1 + lane8);
            A2 = *reinterpret_cast<const uint4*>(T + o2 + lane8);
            A3 = *reinterpret_cast<const uint4*>(T + o3 + lane8);
        }

        {
            const __half2* c0 = reinterpret_cast<const __half2*>(&B0);
            const __half2* c1 = reinterpret_cast<const __half2*>(&B1);
            const __half2* c2 = reinterpret_cast<const __half2*>(&B2);
            const __half2* c3 = reinterpret_cast<const __half2*>(&B3);
            __half2 r[4];
#pragma unroll
            for (int j = 0; j < 4; ++j) {
                __half2 s = __hadd2(__hadd2(c0[j], c1[j]), __hadd2(c2[j], c3[j]));
                r[j] = __hmax2(s, hz);
            }
#pragma unroll
            for (int n = 0; n < NH_; ++n) {
                uint4 gg = *reinterpret_cast<const uint4*>(&g_s[n][lane8 + 256]);
                const __half2* gh = reinterpret_cast<const __half2*>(&gg);
#pragma unroll
                for (int j = 0; j < 4; ++j) acc[n] = __hfma2(gh[j], r[j], acc[n]);
            }
        }

        // ---- folded reduction: 8 h2 -> 1 h2/lane, head = lane>>2 at lane%4==0 ----
        __half2 res[4];
#pragma unroll
        for (int n = 0; n < 4; ++n) {
            __half2 snd = (lane < 16) ? acc[n + 4] : acc[n];
            __half2 kp  = (lane < 16) ? acc[n]     : acc[n + 4];
            res[n] = __hadd2(kp, shfl_xor_h2(snd, 16));
        }
        __half2 r2[2];
#pragma unroll
        for (int n = 0; n < 2; ++n) {
            __half2 snd = ((lane & 8) == 0) ? res[n + 2] : res[n];
            __half2 kp  = ((lane & 8) == 0) ? res[n]     : res[n + 2];
            r2[n] = __hadd2(kp, shfl_xor_h2(snd, 8));
        }
        __half2 fin;
        {
            __half2 snd = ((lane & 4) == 0) ? r2[1] : r2[0];
            __half2 kp  = ((lane & 4) == 0) ? r2[0] : r2[1];
            fin = __hadd2(kp, shfl_xor_h2(snd, 4));
        }
        fin = __hadd2(fin, shfl_xor_h2(fin, 2));
        fin = __hadd2(fin, shfl_xor_h2(fin, 1));
        if ((lane & 3) == 0) {
            const int n = lane >> 2;
            float bd = __low2float(fin) + __high2float(fin);
            float v = (sc[n][kk] + bd) * 0.125f;
            sc[n][kk] = (kk < slen) ? v : -1e30f;
        }
        kk += 8;
    }
    __syncthreads();

    // softmax over k, warp = head
    {
        const int n = warp;
        float mx = -3.4e38f;
#pragma unroll
        for (int j = 0; j < 6; ++j) mx = fmaxf(mx, sc[n][lane + 32 * j]);
#pragma unroll
        for (int s = 16; s > 0; s >>= 1) mx = fmaxf(mx, __shfl_xor_sync(0xffffffffu, mx, s));
        float sum = 0.f;
        float ev[6];
#pragma unroll
        for (int j = 0; j < 6; ++j) {
            ev[j] = __expf(sc[n][lane + 32 * j] - mx);
            sum += ev[j];
        }
#pragma unroll
        for (int s = 16; s > 0; s >>= 1) sum += __shfl_xor_sync(0xffffffffu, sum, s);
        const float inv = 1.f / sum;
#pragma unroll
        for (int j = 0; j < 6; ++j) sc[n][lane + 32 * j] = ev[j] * inv;
    }
    __syncwarp();   // head-n softmax and head-n AV are the same warp

    // out[m, h] = sum_k attn[n,k] * v_half[b,k,h]   (n = warp for h = 2*tid)
    {
        const __half* __restrict__ vb = d_vh + (size_t)b * L_ * H_;
        const int h = tid * 2;
        const int n = warp;
        float oa = 0.f, ob = 0.f, oc = 0.f, od = 0.f;
        float pa = 0.f, pb = 0.f, pc = 0.f, pd = 0.f;
#pragma unroll 2
        for (int k = 0; k < L_; k += 4) {
            const float a0 = sc[n][k],     a1 = sc[n][k + 1];
            const float a2 = sc[n][k + 2], a3 = sc[n][k + 3];
            __half2 v0 = *reinterpret_cast<const __half2*>(vb + (size_t)k * H_ + h);
            __half2 v1 = *reinterpret_cast<const __half2*>(vb + (size_t)(k + 1) * H_ + h);
            __half2 v2 = *reinterpret_cast<const __half2*>(vb + (size_t)(k + 2) * H_ + h);
            __half2 v3 = *reinterpret_cast<const __half2*>(vb + (size_t)(k + 3) * H_ + h);
            float2 f0 = __half22float2(v0);
            float2 f1 = __half22float2(v1);
            float2 f2 = __half22float2(v2);
            float2 f3 = __half22float2(v3);
            oa += a0 * f0.x; pa += a0 * f0.y;
            ob += a1 * f1.x; pb += a1 * f1.y;
            oc += a2 * f2.x; pc += a2 * f2.y;
            od += a3 * f3.x; pd += a3 * f3.y;
        }
        d_attnout[(size_t)m * H_ + h]     = (oa + ob) + (oc + od);
        d_attnout[(size_t)m * H_ + h + 1] = (pa + pb) + (pc + pd);
    }
}

// ---------------- stage 4: output projection, K-split x8 + atomic epilogue ----------------
__global__ void __launch_bounds__(256, 3) k_ff(const float* __restrict__ Wff,
                                               const float* __restrict__ bff,
                                               float* __restrict__ out)
{
    __shared__ SmemTiles st;
    const int c = blockIdx.z;          // K chunk 0..7, 64 each
    gemm_tile<true, true>(&st, d_attnout + c * 64, H_, Wff + c * 64, H_,
                          (c == 0) ? bff : nullptr,
                          out, H_, ML_, H_, 64);
}

// ---------------- launch ----------------
extern "C" void kernel_launch(void* const* d_in, const int* in_sizes, int n_in,
                              void* d_out, int out_size)
{
    (void)n_in; (void)out_size;
    const float* key     = (const float*)d_in[0];
    const float* query   = (const float*)d_in[1];
    const float* value   = (const float*)d_in[2];
    const int*   seq_len = (const int*)d_in[3];
    const int ip = (in_sizes[4] == 1) ? 5 : 4;   // skip lex_num if present
    const int*   pos_s  = (const int*)d_in[ip + 0];
    const int*   pos_e  = (const int*)d_in[ip + 1];
    const float* pe     = (const float*)d_in[ip + 2];
    const float* W_fus  = (const float*)d_in[ip + 3];
    const float* b_fus  = (const float*)d_in[ip + 4];
    const float* Wk     = (const float*)d_in[ip + 5];
    const float* bk     = (const float*)d_in[ip + 6];
    const float* Wq     = (const float*)d_in[ip + 7];
    const float* bq     = (const float*)d_in[ip + 8];
    const float* Wv     = (const float*)d_in[ip + 9];
    const float* bv     = (const float*)d_in[ip + 10];
    const float* Wr     = (const float*)d_in[ip + 11];
    const float* u_bias = (const float*)d_in[ip + 13];
    const float* v_bias = (const float*)d_in[ip + 14];
    const float* Wff    = (const float*)d_in[ip + 15];
    const float* bff    = (const float*)d_in[ip + 16];
    // d_in[ip+12] (br) intentionally unused: constant over k under softmax

    k_proj <<<dim3(8, 6, 3), 256>>>(key, query, value, Wk, bk, Wq, bq, Wv, bv,
                                    u_bias, v_bias);
    k_mid  <<<dim3(8, 6, 29), 256>>>(Wr, pe, W_fus, b_fus, (float*)d_out);
    k_attn <<<ML_, 256>>>(pos_s, pos_e, seq_len);
    k_ff   <<<dim3(8, 6, 8), 256>>>(Wff, bff, (float*)d_out);
}

// round 9
// speedup vs baseline: 1.0972x; 1.0972x over previous
#include <cuda_runtime.h>
#include <cuda_fp16.h>
#include <cstdint>
#include <cstddef>

#define B_    2
#define L_    192
#define H_    512
#define NH_   8
#define ML_   (B_*L_)     // 384 rows (b,l) flattened
#define TROWS_ 383        // distinct position diffs: [-191, 191]
#define SCP_  196         // padded score row (bank-conflict-free 8-lane stores)

// ---------------- scratch (device globals; no allocation allowed) ----------------
static __device__ __align__(16) __half d_Th[4 * TROWS_ * H_];   // 4 pe tables (half; T0 includes b_fus)
static __device__ __align__(16) float  d_kproj[ML_ * H_];
static __device__ __align__(16) float  d_qkA[ML_ * H_];         // qproj + bq + u_bias
static __device__ __align__(16) float  d_u[ML_ * H_];           // qproj + bq + v_bias
static __device__ __align__(16) __half d_vh[ML_ * H_];          // v projection (half)
static __device__ __align__(16) __half d_gh[ML_ * NH_ * H_];    // u_head @ Wr_head (half)
static __device__ __align__(16) float  d_qk[2 * NH_ * L_ * L_]; // per-head (q+u_bias).k
static __device__ __align__(16) float  d_attnout[ML_ * H_];

__device__ __forceinline__ float st_conv(float v, float*)  { return v; }
__device__ __forceinline__ __half st_conv(float v, __half*) { return __float2half(v); }

// ------- tiled SGEMM: 64x64 tile, BK=16, 4x4 microtile, DOUBLE-BUFFERED smem -------
// Inner product uses packed fma.rn.f32x2 (Blackwell 2x fp32 path): rows paired
// (i0,i1),(i2,i3); the a-pair is one LDS.64, b duplicated via mov.b64 {b,b}.
template<bool TRANSB, bool ATOMIC, typename OT>
__device__ __forceinline__ void gemm_tile(
    const float* __restrict__ A, int lda,
    const float* __restrict__ B, int ldb,
    const float* __restrict__ bias,
    OT* __restrict__ C, int ldc,
    int M, int N, int K,
    const float* __restrict__ addA = nullptr,
    float* __restrict__ C2 = nullptr,
    const float* __restrict__ add2 = nullptr)
{
    __shared__ float As[2][16][68];
    __shared__ float Bs[2][16][68];
    const int tid = threadIdx.x;
    const int tx = tid & 15, ty = tid >> 4;
    const int m0 = blockIdx.y * 64, n0 = blockIdx.x * 64;

    unsigned long long acc2[2][4];    // packed {row 2ip, row 2ip+1} x col j
#pragma unroll
    for (int ip = 0; ip < 2; ++ip)
#pragma unroll
        for (int j = 0; j < 4; ++j) acc2[ip][j] = 0ULL;

    const int lm = tid >> 2;          // 0..63
    const int lk = (tid & 3) * 4;     // 0,4,8,12
    const int bk = tid >> 4;          // 0..15 (NN B)
    const int bn = (tid & 15) * 4;    // 0..60

    {
        float4 av = make_float4(0.f, 0.f, 0.f, 0.f);
        if (m0 + lm < M)
            av = *reinterpret_cast<const float4*>(A + (size_t)(m0 + lm) * lda + lk);
        As[0][lk + 0][lm] = av.x; As[0][lk + 1][lm] = av.y;
        As[0][lk + 2][lm] = av.z; As[0][lk + 3][lm] = av.w;
        if (TRANSB) {
            float4 bv = make_float4(0.f, 0.f, 0.f, 0.f);
            if (n0 + lm < N)
                bv = *reinterpret_cast<const float4*>(B + (size_t)(n0 + lm) * ldb + lk);
            Bs[0][lk + 0][lm] = bv.x; Bs[0][lk + 1][lm] = bv.y;
            Bs[0][lk + 2][lm] = bv.z; Bs[0][lk + 3][lm] = bv.w;
        } else {
            float4 bv = make_float4(0.f, 0.f, 0.f, 0.f);
            if (n0 + bn < N)
                bv = *reinterpret_cast<const float4*>(B + (size_t)bk * ldb + n0 + bn);
            *reinterpret_cast<float4*>(&Bs[0][bk][bn]) = bv;
        }
    }
    __syncthreads();

    int buf = 0;
    for (int k0 = 0; k0 < K; k0 += 16) {
        const bool has_next = (k0 + 16 < K);
        float4 av = make_float4(0.f, 0.f, 0.f, 0.f);
        float4 bv = make_float4(0.f, 0.f, 0.f, 0.f);
        if (has_next) {
            const int kn = k0 + 16;
            if (m0 + lm < M)
                av = *reinterpret_cast<const float4*>(A + (size_t)(m0 + lm) * lda + kn + lk);
            if (TRANSB) {
                if (n0 + lm < N)
                    bv = *reinterpret_cast<const float4*>(B + (size_t)(n0 + lm) * ldb + kn + lk);
            } else {
                if (n0 + bn < N)
                    bv = *reinterpret_cast<const float4*>(B + (size_t)(kn + bk) * ldb + n0 + bn);
            }
        }
#pragma unroll
        for (int kk = 0; kk < 16; ++kk) {
            // a rows pair-packed straight from shared (LDS.64, no pack cost)
            unsigned long long a01 = *reinterpret_cast<const unsigned long long*>(&As[buf][kk][ty * 4]);
            unsigned long long a23 = *reinterpret_cast<const unsigned long long*>(&As[buf][kk][ty * 4 + 2]);
            float b0 = Bs[buf][kk][tx * 4 + 0];
            float b1 = Bs[buf][kk][tx * 4 + 1];
            float b2 = Bs[buf][kk][tx * 4 + 2];
            float b3 = Bs[buf][kk][tx * 4 + 3];
            unsigned long long bb0, bb1, bb2, bb3;
            asm("mov.b64 %0, {%1, %1};" : "=l"(bb0) : "f"(b0));
            asm("mov.b64 %0, {%1, %1};" : "=l"(bb1) : "f"(b1));
            asm("mov.b64 %0, {%1, %1};" : "=l"(bb2) : "f"(b2));
            asm("mov.b64 %0, {%1, %1};" : "=l"(bb3) : "f"(b3));
            asm("fma.rn.f32x2 %0, %1, %2, %0;" : "+l"(acc2[0][0]) : "l"(a01), "l"(bb0));
            asm("fma.rn.f32x2 %0, %1, %2, %0;" : "+l"(acc2[0][1]) : "l"(a01), "l"(bb1));
            asm("fma.rn.f32x2 %0, %1, %2, %0;" : "+l"(acc2[0][2]) : "l"(a01), "l"(bb2));
            asm("fma.rn.f32x2 %0, %1, %2, %0;" : "+l"(acc2[0][3]) : "l"(a01), "l"(bb3));
            asm("fma.rn.f32x2 %0, %1, %2, %0;" : "+l"(acc2[1][0]) : "l"(a23), "l"(bb0));
            asm("fma.rn.f32x2 %0, %1, %2, %0;" : "+l"(acc2[1][1]) : "l"(a23), "l"(bb1));
            asm("fma.rn.f32x2 %0, %1, %2, %0;" : "+l"(acc2[1][2]) : "l"(a23), "l"(bb2));
            asm("fma.rn.f32x2 %0, %1, %2, %0;" : "+l"(acc2[1][3]) : "l"(a23), "l"(bb3));
        }
        if (has_next) {
            const int nb = buf ^ 1;
            As[nb][lk + 0][lm] = av.x; As[nb][lk + 1][lm] = av.y;
            As[nb][lk + 2][lm] = av.z; As[nb][lk + 3][lm] = av.w;
            if (TRANSB) {
                Bs[nb][lk + 0][lm] = bv.x; Bs[nb][lk + 1][lm] = bv.y;
                Bs[nb][lk + 2][lm] = bv.z; Bs[nb][lk + 3][lm] = bv.w;
            } else {
                *reinterpret_cast<float4*>(&Bs[nb][bk][bn]) = bv;
            }
        }
        __syncthreads();
        buf ^= 1;
    }

    // unpack packed accumulators
    float acc[4][4];
#pragma unroll
    for (int ip = 0; ip < 2; ++ip)
#pragma unroll
        for (int j = 0; j < 4; ++j) {
            float lo, hi;
            asm("mov.b64 {%0, %1}, %2;" : "=f"(lo), "=f"(hi) : "l"(acc2[ip][j]));
            acc[2 * ip][j] = lo;
            acc[2 * ip + 1][j] = hi;
        }

    const int mo = m0 + ty * 4, no = n0 + tx * 4;
#pragma unroll
    for (int i = 0; i < 4; ++i) {
        if (mo + i < M) {
#pragma unroll
            for (int j = 0; j < 4; ++j) {
                if (no + j < N) {
                    float base = acc[i][j];
                    if (bias) base += bias[no + j];
                    if (ATOMIC) {
                        atomicAdd(reinterpret_cast<float*>(&C[(size_t)(mo + i) * ldc + no + j]), base);
                    } else {
                        float v1 = base;
                        if (addA) v1 += addA[no + j];
                        C[(size_t)(mo + i) * ldc + no + j] = st_conv(v1, (OT*)nullptr);
                        if (C2) C2[(size_t)(mo + i) * ldc + no + j] = base + add2[no + j];
                    }
                }
            }
        }
    }
}

// ---------------- stage 1: projections + pe tables (fused launch, R5 structure) ----------------
__global__ void __launch_bounds__(256) k_pre(
    const float* __restrict__ key, const float* __restrict__ query, const float* __restrict__ value,
    const float* __restrict__ Wk, const float* __restrict__ bk,
    const float* __restrict__ Wq, const float* __restrict__ bq,
    const float* __restrict__ Wv, const float* __restrict__ bv,
    const float* __restrict__ pe, const float* __restrict__ W_fus,
    const float* __restrict__ b_fus,
    const float* __restrict__ u_bias, const float* __restrict__ v_bias)
{
    const int z = blockIdx.z;
    if (z == 0) {
        gemm_tile<true, false>(key, H_, Wk, H_, bk, d_kproj, H_, ML_, H_, H_);
    } else if (z == 1) {
        // dual write: d_qkA = q@Wq^T + bq + u_bias ; d_u = q@Wq^T + bq + v_bias
        gemm_tile<true, false>(query, H_, Wq, H_, bq, d_qkA, H_, ML_, H_, H_,
                               u_bias, d_u, v_bias);
    } else if (z == 2) {
        gemm_tile<true, false>(value, H_, Wv, H_, bv, d_vh, H_, ML_, H_, H_);
    } else {
        const int t = z - 3;   // table 0..3; b_fus folded into T0
        gemm_tile<true, false>(pe + 321 * H_, H_, W_fus + t * 256, 2 * H_,
                               (t == 0) ? b_fus : nullptr,
                               d_Th + (size_t)t * TROWS_ * H_, H_, TROWS_, H_, 256);
    }
}

// -------- stage 2: g (half) + per-head qk GEMMs + early zero of d_out (R5 structure) --------
__global__ void __launch_bounds__(256) k_gqk(const float* __restrict__ Wr,
                                             float* __restrict__ out)
{
    const int z = blockIdx.z;
    if (z < 8) {
        gemm_tile<false, false>(d_u + z * 64, H_, Wr + (size_t)z * 64 * H_, H_, nullptr,
                                d_gh + (size_t)z * H_, NH_ * H_, ML_, H_, 64);
    } else if (z < 24) {
        if (blockIdx.x >= 3 || blockIdx.y >= 3) return;
        const int idx = z - 8;         // b*8 + n
        const int b = idx >> 3, n = idx & 7;
        gemm_tile<true, false>(d_qkA   + (size_t)b * L_ * H_ + n * 64, H_,
                               d_kproj + (size_t)b * L_ * H_ + n * 64, H_, nullptr,
                               d_qk + (size_t)idx * L_ * L_, L_, L_, L_, 64);
    } else {
        // zero d_out for k_ff's atomic accumulation
        const float4 z4 = make_float4(0.f, 0.f, 0.f, 0.f);
        float4* o4 = reinterpret_cast<float4*>(out);
        const int stride = 48 * 256;
        const int start = (blockIdx.y * 8 + blockIdx.x) * 256 + threadIdx.x;
        for (int i = start; i < (ML_ * H_) / 4; i += stride) o4[i] = z4;
    }
}

__device__ __forceinline__ __half2 shfl_xor_h2(__half2 v, int s) {
    unsigned u = *reinterpret_cast<unsigned*>(&v);
    u = __shfl_xor_sync(0xffffffffu, u, s);
    return *reinterpret_cast<__half2*>(&u);
}

// ------ stage 3: fused rel-scores + softmax + attn@V per (b,q)  [R5 pipelined version] ------
__global__ void __launch_bounds__(256, 3) k_attn(
    const int* __restrict__ pos_s,
    const int* __restrict__ pos_e,
    const int* __restrict__ seq_len)
{
    __shared__ __align__(16) __half g_s[NH_][H_];    // 8 KB
    __shared__ __align__(16) float sc[NH_][SCP_];    // padded: 8-lane stores conflict-free
    __shared__ int ksp[L_], kep[L_];

    const int m = blockIdx.x;          // b*L + q
    const int b = m / L_;
    const int qi = m % L_;
    const int tid = threadIdx.x;
    const int lane = tid & 31;
    const int warp = tid >> 5;

    {
        const uint4* src = reinterpret_cast<const uint4*>(d_gh + (size_t)m * (NH_ * H_));
        uint4* dst = reinterpret_cast<uint4*>(&g_s[0][0]);
        for (int i = tid; i < (NH_ * H_) / 8; i += 256) dst[i] = src[i];
    }
    for (int i = tid; i < NH_ * L_; i += 256) {
        const int n = i / L_, k = i % L_;
        sc[n][k] = d_qk[((size_t)(b * NH_ + n) * L_ + qi) * L_ + k];
    }
    for (int i = tid; i < L_; i += 256) { ksp[i] = pos_s[b * L_ + i]; kep[i] = pos_e[b * L_ + i]; }
    const int psq = pos_s[m], peq = pos_e[m];
    const int slen = seq_len[b];
    __syncthreads();

    const __half2 hz = __float2half2_rn(0.f);
    const __half* __restrict__ T = d_Th;
    const int lane8 = lane << 3;

    // --- software-pipelined score loop: warp w handles keys w, w+8, ... ---
    int o0, o1, o2, o3;
    {
        const int kk0 = warp;
        o0 = ((0 * TROWS_ + psq - ksp[kk0] + 191) << 9);
        o1 = ((1 * TROWS_ + psq - kep[kk0] + 191) << 9);
        o2 = ((2 * TROWS_ + peq - ksp[kk0] + 191) << 9);
        o3 = ((3 * TROWS_ + peq - kep[kk0] + 191) << 9);
    }
    uint4 A0 = *reinterpret_cast<const uint4*>(T + o0 + lane8);
    uint4 A1 = *reinterpret_cast<const uint4*>(T + o1 + lane8);
    uint4 A2 = *reinterpret_cast<const uint4*>(T + o2 + lane8);
    uint4 A3 = *reinterpret_cast<const uint4*>(T + o3 + lane8);

    int kk = warp;
#pragma unroll 1
    for (int t = 0; t < 24; ++t) {
        __half2 acc[NH_];
#pragma unroll
        for (int n = 0; n < NH_; ++n) acc[n] = hz;

        // prefetch second chunk of current key
        uint4 B0 = *reinterpret_cast<const uint4*>(T + o0 + lane8 + 256);
        uint4 B1 = *reinterpret_cast<const uint4*>(T + o1 + lane8 + 256);
        uint4 B2 = *reinterpret_cast<const uint4*>(T + o2 + lane8 + 256);
        uint4 B3 = *reinterpret_cast<const uint4*>(T + o3 + lane8 + 256);

        {
            const __half2* c0 = reinterpret_cast<const __half2*>(&A0);
            const __half2* c1 = reinterpret_cast<const __half2*>(&A1);
            const __half2* c2 = reinterpret_cast<const __half2*>(&A2);
            const __half2* c3 = reinterpret_cast<const __half2*>(&A3);
            __half2 r[4];
#pragma unroll
            for (int j = 0; j < 4; ++j) {
                __half2 s = __hadd2(__hadd2(c0[j], c1[j]), __hadd2(c2[j], c3[j]));
                r[j] = __hmax2(s, hz);   // b_fus folded into T0
            }
#pragma unroll
            for (int n = 0; n < NH_; ++n) {
                uint4 gg = *reinterpret_cast<const uint4*>(&g_s[n][lane8]);
                const __half2* gh = reinterpret_cast<const __half2*>(&gg);
#pragma unroll
                for (int j = 0; j < 4; ++j) acc[n] = __hfma2(gh[j], r[j], acc[n]);
            }
        }

        // prefetch first chunk of NEXT key (covers the reduction + chunk-1 compute)
        if (t < 23) {
            const int kn = kk + 8;
            o0 = ((0 * TROWS_ + psq - ksp[kn] + 191) << 9);
            o1 = ((1 * TROWS_ + psq - kep[kn] + 191) << 9);
            o2 = ((2 * TROWS_ + peq - ksp[kn] + 191) << 9);
            o3 = ((3 * TROWS_ + peq - kep[kn] + 191) << 9);
            A0 = *reinterpret_cast<const uint4*>(T + o0 + lane8);
            A1 = *reinterpret_cast<const uint4*>(T + o1 + lane8);
            A2 = *reinterpret_cast<const uint4*>(T + o2 + lane8);
            A3 = *reinterpret_cast<const uint4*>(T + o3 + lane8);
        }

        {
            const __half2* c0 = reinterpret_cast<const __half2*>(&B0);
            const __half2* c1 = reinterpret_cast<const __half2*>(&B1);
            const __half2* c2 = reinterpret_cast<const __half2*>(&B2);
            const __half2* c3 = reinterpret_cast<const __half2*>(&B3);
            __half2 r[4];
#pragma unroll
            for (int j = 0; j < 4; ++j) {
                __half2 s = __hadd2(__hadd2(c0[j], c1[j]), __hadd2(c2[j], c3[j]));
                r[j] = __hmax2(s, hz);
            }
#pragma unroll
            for (int n = 0; n < NH_; ++n) {
                uint4 gg = *reinterpret_cast<const uint4*>(&g_s[n][lane8 + 256]);
                const __half2* gh = reinterpret_cast<const __half2*>(&gg);
#pragma unroll
                for (int j = 0; j < 4; ++j) acc[n] = __hfma2(gh[j], r[j], acc[n]);
            }
        }

        // ---- folded reduction: 8 h2 -> 1 h2/lane, head = lane>>2 at lane%4==0 ----
        __half2 res[4];
#pragma unroll
        for (int n = 0; n < 4; ++n) {
            __half2 snd = (lane < 16) ? acc[n + 4] : acc[n];
            __half2 kp  = (lane < 16) ? acc[n]     : acc[n + 4];
            res[n] = __hadd2(kp, shfl_xor_h2(snd, 16));
        }
        __half2 r2[2];
#pragma unroll
        for (int n = 0; n < 2; ++n) {
            __half2 snd = ((lane & 8) == 0) ? res[n + 2] : res[n];
            __half2 kp  = ((lane & 8) == 0) ? res[n]     : res[n + 2];
            r2[n] = __hadd2(kp, shfl_xor_h2(snd, 8));
        }
        __half2 fin;
        {
            __half2 snd = ((lane & 4) == 0) ? r2[1] : r2[0];
            __half2 kp  = ((lane & 4) == 0) ? r2[0] : r2[1];
            fin = __hadd2(kp, shfl_xor_h2(snd, 4));
        }
        fin = __hadd2(fin, shfl_xor_h2(fin, 2));
        fin = __hadd2(fin, shfl_xor_h2(fin, 1));
        if ((lane & 3) == 0) {
            const int n = lane >> 2;
            float bd = __low2float(fin) + __high2float(fin);
            float v = (sc[n][kk] + bd) * 0.125f;
            sc[n][kk] = (kk < slen) ? v : -1e30f;
        }
        kk += 8;
    }
    __syncthreads();

    // softmax over k, warp = head
    {
        const int n = warp;
        float mx = -3.4e38f;
#pragma unroll
        for (int j = 0; j < 6; ++j) mx = fmaxf(mx, sc[n][lane + 32 * j]);
#pragma unroll
        for (int s = 16; s > 0; s >>= 1) mx = fmaxf(mx, __shfl_xor_sync(0xffffffffu, mx, s));
        float sum = 0.f;
        float ev[6];
#pragma unroll
        for (int j = 0; j < 6; ++j) {
            ev[j] = __expf(sc[n][lane + 32 * j] - mx);
            sum += ev[j];
        }
#pragma unroll
        for (int s = 16; s > 0; s >>= 1) sum += __shfl_xor_sync(0xffffffffu, sum, s);
        const float inv = 1.f / sum;
#pragma unroll
        for (int j = 0; j < 6; ++j) sc[n][lane + 32 * j] = ev[j] * inv;
    }
    __syncwarp();   // head-n softmax and head-n AV are the same warp

    // out[m, h] = sum_k attn[n,k] * v_half[b,k,h]   (n = warp for h = 2*tid)
    {
        const __half* __restrict__ vb = d_vh + (size_t)b * L_ * H_;
        const int h = tid * 2;
        const int n = warp;
        float oa = 0.f, ob = 0.f, oc = 0.f, od = 0.f;
        float pa = 0.f, pb = 0.f, pc = 0.f, pd = 0.f;
#pragma unroll 2
        for (int k = 0; k < L_; k += 4) {
            const float a0 = sc[n][k],     a1 = sc[n][k + 1];
            const float a2 = sc[n][k + 2], a3 = sc[n][k + 3];
            __half2 v0 = *reinterpret_cast<const __half2*>(vb + (size_t)k * H_ + h);
            __half2 v1 = *reinterpret_cast<const __half2*>(vb + (size_t)(k + 1) * H_ + h);
            __half2 v2 = *reinterpret_cast<const __half2*>(vb + (size_t)(k + 2) * H_ + h);
            __half2 v3 = *reinterpret_cast<const __half2*>(vb + (size_t)(k + 3) * H_ + h);
            float2 f0 = __half22float2(v0);
            float2 f1 = __half22float2(v1);
            float2 f2 = __half22float2(v2);
            float2 f3 = __half22float2(v3);
            oa += a0 * f0.x; pa += a0 * f0.y;
            ob += a1 * f1.x; pb += a1 * f1.y;
            oc += a2 * f2.x; pc += a2 * f2.y;
            od += a3 * f3.x; pd += a3 * f3.y;
        }
        d_attnout[(size_t)m * H_ + h]     = (oa + ob) + (oc + od);
        d_attnout[(size_t)m * H_ + h + 1] = (pa + pb) + (pc + pd);
    }
}

// ---------------- stage 4: output projection, K-split x8 + atomic epilogue ----------------
__global__ void __launch_bounds__(256, 3) k_ff(const float* __restrict__ Wff,
                                               const float* __restrict__ bff,
                                               float* __restrict__ out)
{
    const int c = blockIdx.z;          // K chunk 0..7, 64 each
    gemm_tile<true, true>(d_attnout + c * 64, H_, Wff + c * 64, H_,
                          (c == 0) ? bff : nullptr,
                          out, H_, ML_, H_, 64);
}

// ---------------- launch ----------------
extern "C" void kernel_launch(void* const* d_in, const int* in_sizes, int n_in,
                              void* d_out, int out_size)
{
    (void)n_in; (void)out_size;
    const float* key     = (const float*)d_in[0];
    const float* query   = (const float*)d_in[1];
    const float* value   = (const float*)d_in[2];
    const int*   seq_len = (const int*)d_in[3];
    const int ip = (in_sizes[4] == 1) ? 5 : 4;   // skip lex_num if present
    const int*   pos_s  = (const int*)d_in[ip + 0];
    const int*   pos_e  = (const int*)d_in[ip + 1];
    const float* pe     = (const float*)d_in[ip + 2];
    const float* W_fus  = (const float*)d_in[ip + 3];
    const float* b_fus  = (const float*)d_in[ip + 4];
    const float* Wk     = (const float*)d_in[ip + 5];
    const float* bk     = (const float*)d_in[ip + 6];
    const float* Wq     = (const float*)d_in[ip + 7];
    const float* bq     = (const float*)d_in[ip + 8];
    const float* Wv     = (const float*)d_in[ip + 9];
    const float* bv     = (const float*)d_in[ip + 10];
    const float* Wr     = (const float*)d_in[ip + 11];
    const float* u_bias = (const float*)d_in[ip + 13];
    const float* v_bias = (const float*)d_in[ip + 14];
    const float* Wff    = (const float*)d_in[ip + 15];
    const float* bff    = (const float*)d_in[ip + 16];
    // d_in[ip+12] (br) intentionally unused: constant over k under softmax

    k_pre  <<<dim3(8, 6, 7), 256>>>(key, query, value, Wk, bk, Wq, bq, Wv, bv,
                                    pe, W_fus, b_fus, u_bias, v_bias);
    k_gqk  <<<dim3(8, 6, 25), 256>>>(Wr, (float*)d_out);
    k_attn <<<ML_, 256>>>(pos_s, pos_e, seq_len);
    k_ff   <<<dim3(8, 6, 8), 256>>>(Wff, bff, (float*)d_out);
}

// round 11
// speedup vs baseline: 1.4564x; 1.3273x over previous
#include <cuda_runtime.h>
#include <cuda_fp16.h>
#include <cstdint>
#include <cstddef>

#define B_    2
#define L_    192
#define H_    512
#define NH_   8
#define ML_   (B_*L_)     // 384 rows (b,l) flattened
#define TROWS_ 383        // distinct position diffs: [-191, 191]
#define SCP_  196         // padded score row

// ---------------- scratch (device globals; no allocation allowed) ----------------
static __device__ __align__(16) __half d_Th[4 * TROWS_ * H_];   // 4 pe tables (T0 includes b_fus)
static __device__ __align__(16) __half d_kh[ML_ * H_];          // k projection (half)
static __device__ __align__(16) __half d_qkAh[ML_ * H_];        // qproj + bq + u_bias (half)
static __device__ __align__(16) __half d_uh[ML_ * H_];          // qproj + bq + v_bias (half)
static __device__ __align__(16) __half d_vh[ML_ * H_];          // v projection (half)
static __device__ __align__(16) __half d_gh[ML_ * NH_ * H_];    // u_head @ Wr_head (half)
static __device__ __align__(16) __half d_WrTh[NH_ * H_ * 64];   // Wr transposed per head [h][f][d]
static __device__ __align__(16) float  d_qk[2 * NH_ * L_ * L_]; // per-head (q+u_bias).k
static __device__ __align__(16) __half d_attnouth[ML_ * H_];

__device__ __forceinline__ float st_conv(float v, float*)  { return v; }
__device__ __forceinline__ __half st_conv(float v, __half*) { return __float2half(v); }

template<class T, class U> struct is_same_t { static const bool v = false; };
template<class T> struct is_same_t<T, T>    { static const bool v = true;  };

// ---------------- tensor-core HGEMM: 64x64 tile, BK=32, mma.m16n8k16 ----------------
// C[m,n] = sum_k A[m,k] * B[n,k]  (both operands row-major over [row][k])
// fp32 sources convert to half at tile commit (TWO rows/thread: rf and rf+32).
template<typename AT, typename BT, bool ATOMIC, typename OT>
__device__ __forceinline__ void hgemm(
    const AT* __restrict__ A, int lda,
    const BT* __restrict__ B, int ldb,
    const float* __restrict__ bias,
    OT* __restrict__ C, int ldc,
    int M, int N, int K,
    const float* __restrict__ addA = nullptr,
    __half* __restrict__ C2 = nullptr,
    const float* __restrict__ add2 = nullptr)
{
    __shared__ __half As[2][64][40];   // pitch 40 halves (80 B): 16B-aligned rows
    __shared__ __half Bs[2][64][40];
    const int tid  = threadIdx.x;
    const int lane = tid & 31, warp = tid >> 5;
    const int wm = warp >> 1, wn = warp & 1;       // 4 x 2 warp grid
    const int m0 = blockIdx.y * 64, n0 = blockIdx.x * 64;

    float acc[4][4];                   // [n-tile j][mma c-reg]
#pragma unroll
    for (int j = 0; j < 4; ++j)
#pragma unroll
        for (int r = 0; r < 4; ++r) acc[j][r] = 0.f;

    const int rf = tid >> 3, kcf = (tid & 7) * 4;  // fp32 path: rows rf and rf+32
    const int rh = tid >> 2, kch = (tid & 3) * 8;  // half path: 64 rows covered

    float4 afv0, afv1, bfv0, bfv1; uint4 ahv, bhv;

    auto fetchA = [&](int k0) {
        if constexpr (is_same_t<AT, float>::v) {
            const float* Af = reinterpret_cast<const float*>(A);
            afv0 = make_float4(0.f, 0.f, 0.f, 0.f);
            afv1 = make_float4(0.f, 0.f, 0.f, 0.f);
            if (m0 + rf < M)
                afv0 = *reinterpret_cast<const float4*>(Af + (size_t)(m0 + rf) * lda + k0 + kcf);
            if (m0 + rf + 32 < M)
                afv1 = *reinterpret_cast<const float4*>(Af + (size_t)(m0 + rf + 32) * lda + k0 + kcf);
        } else {
            ahv = make_uint4(0u, 0u, 0u, 0u);
            if (m0 + rh < M)
                ahv = *reinterpret_cast<const uint4*>(
                    reinterpret_cast<const __half*>(A) + (size_t)(m0 + rh) * lda + k0 + kch);
        }
    };
    auto fetchB = [&](int k0) {
        if constexpr (is_same_t<BT, float>::v) {
            const float* Bf = reinterpret_cast<const float*>(B);
            bfv0 = make_float4(0.f, 0.f, 0.f, 0.f);
            bfv1 = make_float4(0.f, 0.f, 0.f, 0.f);
            if (n0 + rf < N)
                bfv0 = *reinterpret_cast<const float4*>(Bf + (size_t)(n0 + rf) * ldb + k0 + kcf);
            if (n0 + rf + 32 < N)
                bfv1 = *reinterpret_cast<const float4*>(Bf + (size_t)(n0 + rf + 32) * ldb + k0 + kcf);
        } else {
            bhv = make_uint4(0u, 0u, 0u, 0u);
            if (n0 + rh < N)
                bhv = *reinterpret_cast<const uint4*>(
                    reinterpret_cast<const __half*>(B) + (size_t)(n0 + rh) * ldb + k0 + kch);
        }
    };
    auto packh = [](const float4& f) {
        __half2 h0 = __floats2half2_rn(f.x, f.y);
        __half2 h1 = __floats2half2_rn(f.z, f.w);
        uint2 u;
        u.x = *reinterpret_cast<unsigned*>(&h0);
        u.y = *reinterpret_cast<unsigned*>(&h1);
        return u;
    };
    auto commitA = [&](int buf) {
        if constexpr (is_same_t<AT, float>::v) {
            *reinterpret_cast<uint2*>(&As[buf][rf][kcf])      = packh(afv0);
            *reinterpret_cast<uint2*>(&As[buf][rf + 32][kcf]) = packh(afv1);
        } else {
            *reinterpret_cast<uint4*>(&As[buf][rh][kch]) = ahv;
        }
    };
    auto commitB = [&](int buf) {
        if constexpr (is_same_t<BT, float>::v) {
            *reinterpret_cast<uint2*>(&Bs[buf][rf][kcf])      = packh(bfv0);
            *reinterpret_cast<uint2*>(&Bs[buf][rf + 32][kcf]) = packh(bfv1);
        } else {
            *reinterpret_cast<uint4*>(&Bs[buf][rh][kch]) = bhv;
        }
    };

    fetchA(0); fetchB(0);
    commitA(0); commitB(0);
    __syncthreads();

    const int fr = lane & 15;          // fragment row within 16
    const int fc = (lane >> 4) << 3;   // 0 or 8 (k sub-block)

    int buf = 0;
    for (int k0 = 0; k0 < K; k0 += 32) {
        const bool hn = (k0 + 32 < K);
        if (hn) { fetchA(k0 + 32); fetchB(k0 + 32); }

#pragma unroll
        for (int ks = 0; ks < 2; ++ks) {
            uint32_t a0, a1, a2, a3;
            {
                uint32_t addr = (uint32_t)__cvta_generic_to_shared(
                    &As[buf][wm * 16 + fr][ks * 16 + fc]);
                asm volatile("ldmatrix.sync.aligned.m8n8.x4.shared.b16 {%0,%1,%2,%3}, [%4];"
                             : "=r"(a0), "=r"(a1), "=r"(a2), "=r"(a3) : "r"(addr));
            }
#pragma unroll
            for (int jp = 0; jp < 2; ++jp) {
                uint32_t b0, b1, b2, b3;
                uint32_t addr = (uint32_t)__cvta_generic_to_shared(
                    &Bs[buf][wn * 32 + jp * 16 + fr][ks * 16 + fc]);
                asm volatile("ldmatrix.sync.aligned.m8n8.x4.shared.b16 {%0,%1,%2,%3}, [%4];"
                             : "=r"(b0), "=r"(b1), "=r"(b2), "=r"(b3) : "r"(addr));
                asm volatile("mma.sync.aligned.m16n8k16.row.col.f32.f16.f16.f32 "
                             "{%0,%1,%2,%3}, {%4,%5,%6,%7}, {%8,%9}, {%0,%1,%2,%3};"
                             : "+f"(acc[2 * jp][0]), "+f"(acc[2 * jp][1]),
                               "+f"(acc[2 * jp][2]), "+f"(acc[2 * jp][3])
                             : "r"(a0), "r"(a1), "r"(a2), "r"(a3), "r"(b0), "r"(b2));
                asm volatile("mma.sync.aligned.m16n8k16.row.col.f32.f16.f16.f32 "
                             "{%0,%1,%2,%3}, {%4,%5,%6,%7}, {%8,%9}, {%0,%1,%2,%3};"
                             : "+f"(acc[2 * jp + 1][0]), "+f"(acc[2 * jp + 1][1]),
                               "+f"(acc[2 * jp + 1][2]), "+f"(acc[2 * jp + 1][3])
                             : "r"(a0), "r"(a1), "r"(a2), "r"(a3), "r"(b1), "r"(b3));
            }
        }
        if (hn) { commitA(buf ^ 1); commitB(buf ^ 1); }
        __syncthreads();
        buf ^= 1;
    }

    const int er = lane >> 2;
    const int ec = (lane & 3) * 2;
#pragma unroll
    for (int j = 0; j < 4; ++j) {
        const int colb = n0 + wn * 32 + j * 8 + ec;
#pragma unroll
        for (int rr = 0; rr < 2; ++rr) {
            const int row = m0 + wm * 16 + er + rr * 8;
            if (row < M) {
#pragma unroll
                for (int cc = 0; cc < 2; ++cc) {
                    const int c = colb + cc;
                    if (c < N) {
                        float v = acc[j][rr * 2 + cc];
                        if (bias) v += bias[c];
                        if (ATOMIC) {
                            atomicAdd(reinterpret_cast<float*>(&C[(size_t)row * ldc + c]), v);
                        } else {
                            float v1 = v;
                            if (addA) v1 += addA[c];
                            C[(size_t)row * ldc + c] = st_conv(v1, (OT*)nullptr);
                            if (C2) C2[(size_t)row * ldc + c] = __float2half(v + add2[c]);
                        }
                    }
                }
            }
        }
    }
}

// ---------------- stage 1: projections + pe tables + Wr transpose ----------------
__global__ void __launch_bounds__(256) k_pre(
    const float* __restrict__ key, const float* __restrict__ query, const float* __restrict__ value,
    const float* __restrict__ Wk, const float* __restrict__ bk,
    const float* __restrict__ Wq, const float* __restrict__ bq,
    const float* __restrict__ Wv, const float* __restrict__ bv,
    const float* __restrict__ pe, const float* __restrict__ W_fus,
    const float* __restrict__ b_fus, const float* __restrict__ Wr,
    const float* __restrict__ u_bias, const float* __restrict__ v_bias)
{
    const int z = blockIdx.z;
    if (z == 0) {
        hgemm<float, float, false, __half>(key, H_, Wk, H_, bk, d_kh, H_, ML_, H_, H_);
    } else if (z == 1) {
        hgemm<float, float, false, __half>(query, H_, Wq, H_, bq, d_qkAh, H_, ML_, H_, H_,
                                           u_bias, d_uh, v_bias);
    } else if (z == 2) {
        hgemm<float, float, false, __half>(value, H_, Wv, H_, bv, d_vh, H_, ML_, H_, H_);
    } else if (z < 7) {
        const int t = z - 3;   // tables 0..3; b_fus folded into T0
        hgemm<float, float, false, __half>(pe + 321 * H_, H_, W_fus + t * 256, 2 * H_,
                                           (t == 0) ? b_fus : nullptr,
                                           d_Th + (size_t)t * TROWS_ * H_, H_, TROWS_, H_, 256);
    } else {
        // transpose Wr -> d_WrTh[h][f][d] = Wr[h*64+d][f]   (half)
        const int stride = 48 * 256;
        const int start = (blockIdx.y * 8 + blockIdx.x) * 256 + threadIdx.x;
        for (int i = start; i < NH_ * H_ * 64; i += stride) {
            const int h = i >> 15;
            const int rem = i & 32767;
            const int f = rem >> 6;
            const int d = rem & 63;
            d_WrTh[i] = __float2half(Wr[(size_t)(h * 64 + d) * H_ + f]);
        }
    }
}

// -------- stage 2: g (half) + per-head qk GEMMs + early zero of d_out --------
__global__ void __launch_bounds__(256) k_gqk(float* __restrict__ out)
{
    const int z = blockIdx.z;
    if (z < 8) {
        hgemm<__half, __half, false, __half>(d_uh + z * 64, H_, d_WrTh + (size_t)z * H_ * 64, 64,
                                             nullptr, d_gh + z * H_, NH_ * H_, ML_, H_, 64);
    } else if (z < 24) {
        if (blockIdx.x >= 3 || blockIdx.y >= 3) return;
        const int idx = z - 8;         // b*8 + n
        const int b = idx >> 3, n = idx & 7;
        hgemm<__half, __half, false, float>(d_qkAh + (size_t)b * L_ * H_ + n * 64, H_,
                                            d_kh   + (size_t)b * L_ * H_ + n * 64, H_, nullptr,
                                            d_qk + (size_t)idx * L_ * L_, L_, L_, L_, 64);
    } else {
        const float4 z4 = make_float4(0.f, 0.f, 0.f, 0.f);
        float4* o4 = reinterpret_cast<float4*>(out);
        const int stride = 48 * 256;
        const int start = (blockIdx.y * 8 + blockIdx.x) * 256 + threadIdx.x;
        for (int i = start; i < (ML_ * H_) / 4; i += stride) o4[i] = z4;
    }
}

__device__ __forceinline__ __half2 shfl_xor_h2(__half2 v, int s) {
    unsigned u = *reinterpret_cast<unsigned*>(&v);
    u = __shfl_xor_sync(0xffffffffu, u, s);
    return *reinterpret_cast<__half2*>(&u);
}

// ------ stage 3: fused rel-scores + softmax + attn@V per (b,q) ------
__global__ void __launch_bounds__(256, 3) k_attn(
    const int* __restrict__ pos_s,
    const int* __restrict__ pos_e,
    const int* __restrict__ seq_len)
{
    __shared__ __align__(16) __half g_s[NH_][H_];
    __shared__ __align__(16) float sc[NH_][SCP_];
    __shared__ int ksp[L_], kep[L_];

    const int m = blockIdx.x;          // b*L + q
    const int b = m / L_;
    const int qi = m % L_;
    const int tid = threadIdx.x;
    const int lane = tid & 31;
    const int warp = tid >> 5;

    {
        const uint4* src = reinterpret_cast<const uint4*>(d_gh + (size_t)m * (NH_ * H_));
        uint4* dst = reinterpret_cast<uint4*>(&g_s[0][0]);
        for (int i = tid; i < (NH_ * H_) / 8; i += 256) dst[i] = src[i];
    }
    for (int i = tid; i < NH_ * L_; i += 256) {
        const int n = i / L_, k = i % L_;
        sc[n][k] = d_qk[((size_t)(b * NH_ + n) * L_ + qi) * L_ + k];
    }
    for (int i = tid; i < L_; i += 256) { ksp[i] = pos_s[b * L_ + i]; kep[i] = pos_e[b * L_ + i]; }
    const int psq = pos_s[m], peq = pos_e[m];
    const int slen = seq_len[b];
    __syncthreads();

    const __half2 hz = __float2half2_rn(0.f);
    const __half* __restrict__ T = d_Th;
    const int lane8 = lane << 3;

    int o0, o1, o2, o3;
    {
        const int kk0 = warp;
        o0 = ((0 * TROWS_ + psq - ksp[kk0] + 191) << 9);
        o1 = ((1 * TROWS_ + psq - kep[kk0] + 191) << 9);
        o2 = ((2 * TROWS_ + peq - ksp[kk0] + 191) << 9);
        o3 = ((3 * TROWS_ + peq - kep[kk0] + 191) << 9);
    }
    uint4 A0 = *reinterpret_cast<const uint4*>(T + o0 + lane8);
    uint4 A1 = *reinterpret_cast<const uint4*>(T + o1 + lane8);
    uint4 A2 = *reinterpret_cast<const uint4*>(T + o2 + lane8);
    uint4 A3 = *reinterpret_cast<const uint4*>(T + o3 + lane8);

    int kk = warp;
#pragma unroll 1
    for (int t = 0; t < 24; ++t) {
        __half2 acc[NH_];
#pragma unroll
        for (int n = 0; n < NH_; ++n) acc[n] = hz;

        uint4 B0 = *reinterpret_cast<const uint4*>(T + o0 + lane8 + 256);
        uint4 B1 = *reinterpret_cast<const uint4*>(T + o1 + lane8 + 256);
        uint4 B2 = *reinterpret_cast<const uint4*>(T + o2 + lane8 + 256);
        uint4 B3 = *reinterpret_cast<const uint4*>(T + o3 + lane8 + 256);

        {
            const __half2* c0 = reinterpret_cast<const __half2*>(&A0);
            const __half2* c1 = reinterpret_cast<const __half2*>(&A1);
            const __half2* c2 = reinterpret_cast<const __half2*>(&A2);
            const __half2* c3 = reinterpret_cast<const __half2*>(&A3);
            __half2 r[4];
#pragma unroll
            for (int j = 0; j < 4; ++j) {
                __half2 s = __hadd2(__hadd2(c0[j], c1[j]), __hadd2(c2[j], c3[j]));
                r[j] = __hmax2(s, hz);
            }
#pragma unroll
            for (int n = 0; n < NH_; ++n) {
                uint4 gg = *reinterpret_cast<const uint4*>(&g_s[n][lane8]);
                const __half2* gh = reinterpret_cast<const __half2*>(&gg);
#pragma unroll
                for (int j = 0; j < 4; ++j) acc[n] = __hfma2(gh[j], r[j], acc[n]);
            }
        }

        if (t < 23) {
            const int kn = kk + 8;
            o0 = ((0 * TROWS_ + psq - ksp[kn] + 191) << 9);
            o1 = ((1 * TROWS_ + psq - kep[kn] + 191) << 9);
            o2 = ((2 * TROWS_ + peq - ksp[kn] + 191) << 9);
            o3 = ((3 * TROWS_ + peq - kep[kn] + 191) << 9);
            A0 = *reinterpret_cast<const uint4*>(T + o0 + lane8);
            A1 = *reinterpret_cast<const uint4*>(T + o1 + lane8);
            A2 = *reinterpret_cast<const uint4*>(T + o2 + lane8);
            A3 = *reinterpret_cast<const uint4*>(T + o3 + lane8);
        }

        {
            const __half2* c0 = reinterpret_cast<const __half2*>(&B0);
            const __half2* c1 = reinterpret_cast<const __half2*>(&B1);
            const __half2* c2 = reinterpret_cast<const __half2*>(&B2);
            const __half2* c3 = reinterpret_cast<const __half2*>(&B3);
            __half2 r[4];
#pragma unroll
            for (int j = 0; j < 4; ++j) {
                __half2 s = __hadd2(__hadd2(c0[j], c1[j]), __hadd2(c2[j], c3[j]));
                r[j] = __hmax2(s, hz);
            }
#pragma unroll
            for (int n = 0; n < NH_; ++n) {
                uint4 gg = *reinterpret_cast<const uint4*>(&g_s[n][lane8 + 256]);
                const __half2* gh = reinterpret_cast<const __half2*>(&gg);
#pragma unroll
                for (int j = 0; j < 4; ++j) acc[n] = __hfma2(gh[j], r[j], acc[n]);
            }
        }

        __half2 res[4];
#pragma unroll
        for (int n = 0; n < 4; ++n) {
            __half2 snd = (lane < 16) ? acc[n + 4] : acc[n];
            __half2 kp  = (lane < 16) ? acc[n]     : acc[n + 4];
            res[n] = __hadd2(kp, shfl_xor_h2(snd, 16));
        }
        __half2 r2[2];
#pragma unroll
        for (int n = 0; n < 2; ++n) {
            __half2 snd = ((lane & 8) == 0) ? res[n + 2] : res[n];
            __half2 kp  = ((lane & 8) == 0) ? res[n]     : res[n + 2];
            r2[n] = __hadd2(kp, shfl_xor_h2(snd, 8));
        }
        __half2 fin;
        {
            __half2 snd = ((lane & 4) == 0) ? r2[1] : r2[0];
            __half2 kp  = ((lane & 4) == 0) ? r2[0] : r2[1];
            fin = __hadd2(kp, shfl_xor_h2(snd, 4));
        }
        fin = __hadd2(fin, shfl_xor_h2(fin, 2));
        fin = __hadd2(fin, shfl_xor_h2(fin, 1));
        if ((lane & 3) == 0) {
            const int n = lane >> 2;
            float bd = __low2float(fin) + __high2float(fin);
            float v = (sc[n][kk] + bd) * 0.125f;
            sc[n][kk] = (kk < slen) ? v : -1e30f;
        }
        kk += 8;
    }
    __syncthreads();

    // softmax over k, warp = head
    {
        const int n = warp;
        float mx = -3.4e38f;
#pragma unroll
        for (int j = 0; j < 6; ++j) mx = fmaxf(mx, sc[n][lane + 32 * j]);
#pragma unroll
        for (int s = 16; s > 0; s >>= 1) mx = fmaxf(mx, __shfl_xor_sync(0xffffffffu, mx, s));
        float sum = 0.f;
        float ev[6];
#pragma unroll
        for (int j = 0; j < 6; ++j) {
            ev[j] = __expf(sc[n][lane + 32 * j] - mx);
            sum += ev[j];
        }
#pragma unroll
        for (int s = 16; s > 0; s >>= 1) sum += __shfl_xor_sync(0xffffffffu, sum, s);
        const float inv = 1.f / sum;
#pragma unroll
        for (int j = 0; j < 6; ++j) sc[n][lane + 32 * j] = ev[j] * inv;
    }
    __syncwarp();

    // out[m, h] = sum_k attn[n,k] * v_half[b,k,h]  -> stored HALF for tensor-core k_ff
    {
        const __half* __restrict__ vb = d_vh + (size_t)b * L_ * H_;
        const int h = tid * 2;
        const int n = warp;
        float oa = 0.f, ob = 0.f, oc = 0.f, od = 0.f;
        float pa = 0.f, pb = 0.f, pc = 0.f, pd = 0.f;
#pragma unroll 2
        for (int k = 0; k < L_; k += 4) {
            const float a0 = sc[n][k],     a1 = sc[n][k + 1];
            const float a2 = sc[n][k + 2], a3 = sc[n][k + 3];
            __half2 v0 = *reinterpret_cast<const __half2*>(vb + (size_t)k * H_ + h);
            __half2 v1 = *reinterpret_cast<const __half2*>(vb + (size_t)(k + 1) * H_ + h);
            __half2 v2 = *reinterpret_cast<const __half2*>(vb + (size_t)(k + 2) * H_ + h);
            __half2 v3 = *reinterpret_cast<const __half2*>(vb + (size_t)(k + 3) * H_ + h);
            float2 f0 = __half22float2(v0);
            float2 f1 = __half22float2(v1);
            float2 f2 = __half22float2(v2);
            float2 f3 = __half22float2(v3);
            oa += a0 * f0.x; pa += a0 * f0.y;
            ob += a1 * f1.x; pb += a1 * f1.y;
            oc += a2 * f2.x; pc += a2 * f2.y;
            od += a3 * f3.x; pd += a3 * f3.y;
        }
        *reinterpret_cast<__half2*>(d_attnouth + (size_t)m * H_ + h) =
            __floats2half2_rn((oa + ob) + (oc + od), (pa + pb) + (pc + pd));
    }
}

// ---------------- stage 4: output projection, K-split x8 + atomic epilogue ----------------
__global__ void __launch_bounds__(256) k_ff(const float* __restrict__ Wff,
                                            const float* __restrict__ bff,
                                            float* __restrict__ out)
{
    const int c = blockIdx.z;          // K chunk 0..7, 64 each
    hgemm<__half, float, true, float>(d_attnouth + c * 64, H_, Wff + c * 64, H_,
                                      (c == 0) ? bff : nullptr,
                                      out, H_, ML_, H_, 64);
}

// ---------------- launch ----------------
extern "C" void kernel_launch(void* const* d_in, const int* in_sizes, int n_in,
                              void* d_out, int out_size)
{
    (void)n_in; (void)out_size;
    const float* key     = (const float*)d_in[0];
    const float* query   = (const float*)d_in[1];
    const float* value   = (const float*)d_in[2];
    const int*   seq_len = (const int*)d_in[3];
    const int ip = (in_sizes[4] == 1) ? 5 : 4;   // skip lex_num if present
    const int*   pos_s  = (const int*)d_in[ip + 0];
    const int*   pos_e  = (const int*)d_in[ip + 1];
    const float* pe     = (const float*)d_in[ip + 2];
    const float* W_fus  = (const float*)d_in[ip + 3];
    const float* b_fus  = (const float*)d_in[ip + 4];
    const float* Wk     = (const float*)d_in[ip + 5];
    const float* bk     = (const float*)d_in[ip + 6];
    const float* Wq     = (const float*)d_in[ip + 7];
    const float* bq     = (const float*)d_in[ip + 8];
    const float* Wv     = (const float*)d_in[ip + 9];
    const float* bv     = (const float*)d_in[ip + 10];
    const float* Wr     = (const float*)d_in[ip + 11];
    const float* u_bias = (const float*)d_in[ip + 13];
    const float* v_bias = (const float*)d_in[ip + 14];
    const float* Wff    = (const float*)d_in[ip + 15];
    const float* bff    = (const float*)d_in[ip + 16];
    // d_in[ip+12] (br) intentionally unused: constant over k under softmax

    k_pre  <<<dim3(8, 6, 8), 256>>>(key, query, value, Wk, bk, Wq, bq, Wv, bv,
                                    pe, W_fus, b_fus, Wr, u_bias, v_bias);
    k_gqk  <<<dim3(8, 6, 25), 256>>>((float*)d_out);
    k_attn <<<ML_, 256>>>(pos_s, pos_e, seq_len);
    k_ff   <<<dim3(8, 6, 8), 256>>>(Wff, bff, (float*)d_out);
}

// round 12
// speedup vs baseline: 2.4506x; 1.6827x over previous
#include <cuda_runtime.h>
#include <cuda_fp16.h>
#include <cstdint>
#include <cstddef>

#define B_    2
#define L_    192
#define H_    512
#define NH_   8
#define ML_   (B_*L_)     // 384 rows (b,l) flattened
#define TROWS_ 383        // distinct position diffs: [-191, 191]
#define SCP_  196         // padded score row
#define GP_   520         // padded half row (1040B) -> conflict-free ldmatrix

// ---------------- scratch (device globals; no allocation allowed) ----------------
static __device__ __align__(16) __half d_Th[4 * TROWS_ * H_];   // 4 pe tables (T0 includes b_fus)
static __device__ __align__(16) __half d_kh[ML_ * H_];          // k projection (half)
static __device__ __align__(16) __half d_qkAh[ML_ * H_];        // qproj + bq + u_bias (half)
static __device__ __align__(16) __half d_uh[ML_ * H_];          // qproj + bq + v_bias (half)
static __device__ __align__(16) __half d_vh[ML_ * H_];          // v projection (half)
static __device__ __align__(16) __half d_gh[ML_ * NH_ * H_];    // u_head @ Wr_head (half)
static __device__ __align__(16) __half d_WrTh[NH_ * H_ * 64];   // Wr transposed per head [h][f][d]
static __device__ __align__(16) float  d_qk[2 * NH_ * L_ * L_]; // per-head (q+u_bias).k
static __device__ __align__(16) __half d_attnouth[ML_ * H_];

__device__ __forceinline__ float st_conv(float v, float*)  { return v; }
__device__ __forceinline__ __half st_conv(float v, __half*) { return __float2half(v); }

template<class T, class U> struct is_same_t { static const bool v = false; };
template<class T> struct is_same_t<T, T>    { static const bool v = true;  };

// ---------------- tensor-core HGEMM: 64x64 tile, BK=32, mma.m16n8k16 ----------------
// C[m,n] = sum_k A[m,k] * B[n,k]  (both operands row-major over [row][k])
// fp32 sources convert to half at tile commit (TWO rows/thread: rf and rf+32).
template<typename AT, typename BT, bool ATOMIC, typename OT>
__device__ __forceinline__ void hgemm(
    const AT* __restrict__ A, int lda,
    const BT* __restrict__ B, int ldb,
    const float* __restrict__ bias,
    OT* __restrict__ C, int ldc,
    int M, int N, int K,
    const float* __restrict__ addA = nullptr,
    __half* __restrict__ C2 = nullptr,
    const float* __restrict__ add2 = nullptr)
{
    __shared__ __half As[2][64][40];
    __shared__ __half Bs[2][64][40];
    const int tid  = threadIdx.x;
    const int lane = tid & 31, warp = tid >> 5;
    const int wm = warp >> 1, wn = warp & 1;       // 4 x 2 warp grid
    const int m0 = blockIdx.y * 64, n0 = blockIdx.x * 64;

    float acc[4][4];
#pragma unroll
    for (int j = 0; j < 4; ++j)
#pragma unroll
        for (int r = 0; r < 4; ++r) acc[j][r] = 0.f;

    const int rf = tid >> 3, kcf = (tid & 7) * 4;  // fp32 path: rows rf and rf+32
    const int rh = tid >> 2, kch = (tid & 3) * 8;  // half path

    float4 afv0, afv1, bfv0, bfv1; uint4 ahv, bhv;

    auto fetchA = [&](int k0) {
        if constexpr (is_same_t<AT, float>::v) {
            const float* Af = reinterpret_cast<const float*>(A);
            afv0 = make_float4(0.f, 0.f, 0.f, 0.f);
            afv1 = make_float4(0.f, 0.f, 0.f, 0.f);
            if (m0 + rf < M)
                afv0 = *reinterpret_cast<const float4*>(Af + (size_t)(m0 + rf) * lda + k0 + kcf);
            if (m0 + rf + 32 < M)
                afv1 = *reinterpret_cast<const float4*>(Af + (size_t)(m0 + rf + 32) * lda + k0 + kcf);
        } else {
            ahv = make_uint4(0u, 0u, 0u, 0u);
            if (m0 + rh < M)
                ahv = *reinterpret_cast<const uint4*>(
                    reinterpret_cast<const __half*>(A) + (size_t)(m0 + rh) * lda + k0 + kch);
        }
    };
    auto fetchB = [&](int k0) {
        if constexpr (is_same_t<BT, float>::v) {
            const float* Bf = reinterpret_cast<const float*>(B);
            bfv0 = make_float4(0.f, 0.f, 0.f, 0.f);
            bfv1 = make_float4(0.f, 0.f, 0.f, 0.f);
            if (n0 + rf < N)
                bfv0 = *reinterpret_cast<const float4*>(Bf + (size_t)(n0 + rf) * ldb + k0 + kcf);
            if (n0 + rf + 32 < N)
                bfv1 = *reinterpret_cast<const float4*>(Bf + (size_t)(n0 + rf + 32) * ldb + k0 + kcf);
        } else {
            bhv = make_uint4(0u, 0u, 0u, 0u);
            if (n0 + rh < N)
                bhv = *reinterpret_cast<const uint4*>(
                    reinterpret_cast<const __half*>(B) + (size_t)(n0 + rh) * ldb + k0 + kch);
        }
    };
    auto packh = [](const float4& f) {
        __half2 h0 = __floats2half2_rn(f.x, f.y);
        __half2 h1 = __floats2half2_rn(f.z, f.w);
        uint2 u;
        u.x = *reinterpret_cast<unsigned*>(&h0);
        u.y = *reinterpret_cast<unsigned*>(&h1);
        return u;
    };
    auto commitA = [&](int buf) {
        if constexpr (is_same_t<AT, float>::v) {
            *reinterpret_cast<uint2*>(&As[buf][rf][kcf])      = packh(afv0);
            *reinterpret_cast<uint2*>(&As[buf][rf + 32][kcf]) = packh(afv1);
        } else {
            *reinterpret_cast<uint4*>(&As[buf][rh][kch]) = ahv;
        }
    };
    auto commitB = [&](int buf) {
        if constexpr (is_same_t<BT, float>::v) {
            *reinterpret_cast<uint2*>(&Bs[buf][rf][kcf])      = packh(bfv0);
            *reinterpret_cast<uint2*>(&Bs[buf][rf + 32][kcf]) = packh(bfv1);
        } else {
            *reinterpret_cast<uint4*>(&Bs[buf][rh][kch]) = bhv;
        }
    };

    fetchA(0); fetchB(0);
    commitA(0); commitB(0);
    __syncthreads();

    const int fr = lane & 15;
    const int fc = (lane >> 4) << 3;

    int buf = 0;
    for (int k0 = 0; k0 < K; k0 += 32) {
        const bool hn = (k0 + 32 < K);
        if (hn) { fetchA(k0 + 32); fetchB(k0 + 32); }

#pragma unroll
        for (int ks = 0; ks < 2; ++ks) {
            uint32_t a0, a1, a2, a3;
            {
                uint32_t addr = (uint32_t)__cvta_generic_to_shared(
                    &As[buf][wm * 16 + fr][ks * 16 + fc]);
                asm volatile("ldmatrix.sync.aligned.m8n8.x4.shared.b16 {%0,%1,%2,%3}, [%4];"
                             : "=r"(a0), "=r"(a1), "=r"(a2), "=r"(a3) : "r"(addr));
            }
#pragma unroll
            for (int jp = 0; jp < 2; ++jp) {
                uint32_t b0, b1, b2, b3;
                uint32_t addr = (uint32_t)__cvta_generic_to_shared(
                    &Bs[buf][wn * 32 + jp * 16 + fr][ks * 16 + fc]);
                asm volatile("ldmatrix.sync.aligned.m8n8.x4.shared.b16 {%0,%1,%2,%3}, [%4];"
                             : "=r"(b0), "=r"(b1), "=r"(b2), "=r"(b3) : "r"(addr));
                asm volatile("mma.sync.aligned.m16n8k16.row.col.f32.f16.f16.f32 "
                             "{%0,%1,%2,%3}, {%4,%5,%6,%7}, {%8,%9}, {%0,%1,%2,%3};"
                             : "+f"(acc[2 * jp][0]), "+f"(acc[2 * jp][1]),
                               "+f"(acc[2 * jp][2]), "+f"(acc[2 * jp][3])
                             : "r"(a0), "r"(a1), "r"(a2), "r"(a3), "r"(b0), "r"(b2));
                asm volatile("mma.sync.aligned.m16n8k16.row.col.f32.f16.f16.f32 "
                             "{%0,%1,%2,%3}, {%4,%5,%6,%7}, {%8,%9}, {%0,%1,%2,%3};"
                             : "+f"(acc[2 * jp + 1][0]), "+f"(acc[2 * jp + 1][1]),
                               "+f"(acc[2 * jp + 1][2]), "+f"(acc[2 * jp + 1][3])
                             : "r"(a0), "r"(a1), "r"(a2), "r"(a3), "r"(b1), "r"(b3));
            }
        }
        if (hn) { commitA(buf ^ 1); commitB(buf ^ 1); }
        __syncthreads();
        buf ^= 1;
    }

    const int er = lane >> 2;
    const int ec = (lane & 3) * 2;
#pragma unroll
    for (int j = 0; j < 4; ++j) {
        const int colb = n0 + wn * 32 + j * 8 + ec;
#pragma unroll
        for (int rr = 0; rr < 2; ++rr) {
            const int row = m0 + wm * 16 + er + rr * 8;
            if (row < M) {
#pragma unroll
                for (int cc = 0; cc < 2; ++cc) {
                    const int c = colb + cc;
                    if (c < N) {
                        float v = acc[j][rr * 2 + cc];
                        if (bias) v += bias[c];
                        if (ATOMIC) {
                            atomicAdd(reinterpret_cast<float*>(&C[(size_t)row * ldc + c]), v);
                        } else {
                            float v1 = v;
                            if (addA) v1 += addA[c];
                            C[(size_t)row * ldc + c] = st_conv(v1, (OT*)nullptr);
                            if (C2) C2[(size_t)row * ldc + c] = __float2half(v + add2[c]);
                        }
                    }
                }
            }
        }
    }
}

// ---------------- stage 1: projections + pe tables + Wr transpose ----------------
__global__ void __launch_bounds__(256) k_pre(
    const float* __restrict__ key, const float* __restrict__ query, const float* __restrict__ value,
    const float* __restrict__ Wk, const float* __restrict__ bk,
    const float* __restrict__ Wq, const float* __restrict__ bq,
    const float* __restrict__ Wv, const float* __restrict__ bv,
    const float* __restrict__ pe, const float* __restrict__ W_fus,
    const float* __restrict__ b_fus, const float* __restrict__ Wr,
    const float* __restrict__ u_bias, const float* __restrict__ v_bias)
{
    const int z = blockIdx.z;
    if (z == 0) {
        hgemm<float, float, false, __half>(key, H_, Wk, H_, bk, d_kh, H_, ML_, H_, H_);
    } else if (z == 1) {
        hgemm<float, float, false, __half>(query, H_, Wq, H_, bq, d_qkAh, H_, ML_, H_, H_,
                                           u_bias, d_uh, v_bias);
    } else if (z == 2) {
        hgemm<float, float, false, __half>(value, H_, Wv, H_, bv, d_vh, H_, ML_, H_, H_);
    } else if (z < 7) {
        const int t = z - 3;   // tables 0..3; b_fus folded into T0
        hgemm<float, float, false, __half>(pe + 321 * H_, H_, W_fus + t * 256, 2 * H_,
                                           (t == 0) ? b_fus : nullptr,
                                           d_Th + (size_t)t * TROWS_ * H_, H_, TROWS_, H_, 256);
    } else {
        // transpose Wr -> d_WrTh[h][f][d] = Wr[h*64+d][f]   (half)
        const int stride = 48 * 256;
        const int start = (blockIdx.y * 8 + blockIdx.x) * 256 + threadIdx.x;
        for (int i = start; i < NH_ * H_ * 64; i += stride) {
            const int h = i >> 15;
            const int rem = i & 32767;
            const int f = rem >> 6;
            const int d = rem & 63;
            d_WrTh[i] = __float2half(Wr[(size_t)(h * 64 + d) * H_ + f]);
        }
    }
}

// -------- stage 2: g (half) + per-head qk GEMMs + early zero of d_out --------
__global__ void __launch_bounds__(256) k_gqk(float* __restrict__ out)
{
    const int z = blockIdx.z;
    if (z < 8) {
        hgemm<__half, __half, false, __half>(d_uh + z * 64, H_, d_WrTh + (size_t)z * H_ * 64, 64,
                                             nullptr, d_gh + z * H_, NH_ * H_, ML_, H_, 64);
    } else if (z < 24) {
        if (blockIdx.x >= 3 || blockIdx.y >= 3) return;
        const int idx = z - 8;         // b*8 + n
        const int b = idx >> 3, n = idx & 7;
        hgemm<__half, __half, false, float>(d_qkAh + (size_t)b * L_ * H_ + n * 64, H_,
                                            d_kh   + (size_t)b * L_ * H_ + n * 64, H_, nullptr,
                                            d_qk + (size_t)idx * L_ * L_, L_, L_, L_, 64);
    } else {
        const float4 z4 = make_float4(0.f, 0.f, 0.f, 0.f);
        float4* o4 = reinterpret_cast<float4*>(out);
        const int stride = 48 * 256;
        const int start = (blockIdx.y * 8 + blockIdx.x) * 256 + threadIdx.x;
        for (int i = start; i < (ML_ * H_) / 4; i += stride) o4[i] = z4;
    }
}

// ------ stage 3: fused rel-scores (TENSOR-CORE) + softmax + attn@V per (b,q) ------
// Per 16-key chunk: Phase A gathers 4 table rows per key, relu -> smem R[16][GP_];
// Phase B computes scores[16,8] += R[16,512] @ g[512,8] via mma, atomically into sc.
__global__ void __launch_bounds__(256, 3) k_attn(
    const int* __restrict__ pos_s,
    const int* __restrict__ pos_e,
    const int* __restrict__ seq_len)
{
    __shared__ __align__(16) __half g_s[NH_][GP_];   // padded for ldmatrix
    __shared__ __align__(16) __half R[16][GP_];      // relu tile for one key chunk
    __shared__ __align__(16) float sc[NH_][SCP_];
    __shared__ int ksp[L_], kep[L_];

    const int m = blockIdx.x;          // b*L + q
    const int b = m / L_;
    const int qi = m % L_;
    const int tid = threadIdx.x;
    const int lane = tid & 31;
    const int warp = tid >> 5;

    // g tile (row-wise copy due to padding)
    for (int i = tid; i < (NH_ * H_) / 8; i += 256) {
        const int n = i >> 6;          // 64 uint4 per 512-half row
        const int c = i & 63;
        *reinterpret_cast<uint4*>(&g_s[n][c * 8]) =
            *reinterpret_cast<const uint4*>(d_gh + (size_t)m * (NH_ * H_) + n * H_ + c * 8);
    }
    for (int i = tid; i < NH_ * L_; i += 256) {
        const int n = i / L_, k = i % L_;
        sc[n][k] = d_qk[((size_t)(b * NH_ + n) * L_ + qi) * L_ + k];
    }
    for (int i = tid; i < L_; i += 256) { ksp[i] = pos_s[b * L_ + i]; kep[i] = pos_e[b * L_ + i]; }
    const int psq = pos_s[m], peq = pos_e[m];
    const int slen = seq_len[b];
    __syncthreads();

    const __half2 hz = __float2half2_rn(0.f);
    const __half* __restrict__ T = d_Th;
    const int lane8 = lane << 3;
    const int fr = lane & 15;
    const int fc = (lane >> 4) << 3;
    const int er = lane >> 2;
    const int ec = (lane & 3) * 2;

#pragma unroll 1
    for (int ch = 0; ch < 12; ++ch) {
        const int kb = ch * 16;
        // ---- Phase A: build R for 16 keys (2 per warp) ----
#pragma unroll
        for (int e = 0; e < 2; ++e) {
            const int kl = warp * 2 + e;       // local key 0..15
            const int kk = kb + kl;
            const int o0 = ((0 * TROWS_ + psq - ksp[kk] + 191) << 9);
            const int o1 = ((1 * TROWS_ + psq - kep[kk] + 191) << 9);
            const int o2 = ((2 * TROWS_ + peq - ksp[kk] + 191) << 9);
            const int o3 = ((3 * TROWS_ + peq - kep[kk] + 191) << 9);
            uint4 A0 = *reinterpret_cast<const uint4*>(T + o0 + lane8);
            uint4 A1 = *reinterpret_cast<const uint4*>(T + o1 + lane8);
            uint4 A2 = *reinterpret_cast<const uint4*>(T + o2 + lane8);
            uint4 A3 = *reinterpret_cast<const uint4*>(T + o3 + lane8);
            uint4 B0 = *reinterpret_cast<const uint4*>(T + o0 + lane8 + 256);
            uint4 B1 = *reinterpret_cast<const uint4*>(T + o1 + lane8 + 256);
            uint4 B2 = *reinterpret_cast<const uint4*>(T + o2 + lane8 + 256);
            uint4 B3 = *reinterpret_cast<const uint4*>(T + o3 + lane8 + 256);
            {
                const __half2* c0 = reinterpret_cast<const __half2*>(&A0);
                const __half2* c1 = reinterpret_cast<const __half2*>(&A1);
                const __half2* c2 = reinterpret_cast<const __half2*>(&A2);
                const __half2* c3 = reinterpret_cast<const __half2*>(&A3);
                __half2 r[4];
#pragma unroll
                for (int j = 0; j < 4; ++j) {
                    __half2 s = __hadd2(__hadd2(c0[j], c1[j]), __hadd2(c2[j], c3[j]));
                    r[j] = __hmax2(s, hz);
                }
                *reinterpret_cast<uint4*>(&R[kl][lane8]) = *reinterpret_cast<uint4*>(r);
            }
            {
                const __half2* c0 = reinterpret_cast<const __half2*>(&B0);
                const __half2* c1 = reinterpret_cast<const __half2*>(&B1);
                const __half2* c2 = reinterpret_cast<const __half2*>(&B2);
                const __half2* c3 = reinterpret_cast<const __half2*>(&B3);
                __half2 r[4];
#pragma unroll
                for (int j = 0; j < 4; ++j) {
                    __half2 s = __hadd2(__hadd2(c0[j], c1[j]), __hadd2(c2[j], c3[j]));
                    r[j] = __hmax2(s, hz);
                }
                *reinterpret_cast<uint4*>(&R[kl][256 + lane8]) = *reinterpret_cast<uint4*>(r);
            }
        }
        __syncthreads();

        // ---- Phase B: scores[16,8] += R @ g^T ; warp owns 4 k-steps ----
        {
            float acc[4] = {0.f, 0.f, 0.f, 0.f};
#pragma unroll
            for (int ks = 0; ks < 4; ++ks) {
                const int kd = (warp * 4 + ks) * 16;
                uint32_t a0, a1, a2, a3;
                uint32_t addrA = (uint32_t)__cvta_generic_to_shared(&R[fr][kd + fc]);
                asm volatile("ldmatrix.sync.aligned.m8n8.x4.shared.b16 {%0,%1,%2,%3}, [%4];"
                             : "=r"(a0), "=r"(a1), "=r"(a2), "=r"(a3) : "r"(addrA));
                uint32_t b0, b1;
                uint32_t addrB = (uint32_t)__cvta_generic_to_shared(
                    &g_s[lane & 7][kd + ((lane >> 3) & 1) * 8]);
                asm volatile("ldmatrix.sync.aligned.m8n8.x2.shared.b16 {%0,%1}, [%2];"
                             : "=r"(b0), "=r"(b1) : "r"(addrB));
                asm volatile("mma.sync.aligned.m16n8k16.row.col.f32.f16.f16.f32 "
                             "{%0,%1,%2,%3}, {%4,%5,%6,%7}, {%8,%9}, {%0,%1,%2,%3};"
                             : "+f"(acc[0]), "+f"(acc[1]), "+f"(acc[2]), "+f"(acc[3])
                             : "r"(a0), "r"(a1), "r"(a2), "r"(a3), "r"(b0), "r"(b1));
            }
            atomicAdd(&sc[ec][kb + er], acc[0]);
            atomicAdd(&sc[ec + 1][kb + er], acc[1]);
            atomicAdd(&sc[ec][kb + er + 8], acc[2]);
            atomicAdd(&sc[ec + 1][kb + er + 8], acc[3]);
        }
        __syncthreads();
    }

    // scale + mask pass
    for (int i = tid; i < NH_ * L_; i += 256) {
        const int n = i / L_, k = i % L_;
        const float v = sc[n][k] * 0.125f;
        sc[n][k] = (k < slen) ? v : -1e30f;
    }
    __syncthreads();

    // softmax over k, warp = head
    {
        const int n = warp;
        float mx = -3.4e38f;
#pragma unroll
        for (int j = 0; j < 6; ++j) mx = fmaxf(mx, sc[n][lane + 32 * j]);
#pragma unroll
        for (int s = 16; s > 0; s >>= 1) mx = fmaxf(mx, __shfl_xor_sync(0xffffffffu, mx, s));
        float sum = 0.f;
        float ev[6];
#pragma unroll
        for (int j = 0; j < 6; ++j) {
            ev[j] = __expf(sc[n][lane + 32 * j] - mx);
            sum += ev[j];
        }
#pragma unroll
        for (int s = 16; s > 0; s >>= 1) sum += __shfl_xor_sync(0xffffffffu, sum, s);
        const float inv = 1.f / sum;
#pragma unroll
        for (int j = 0; j < 6; ++j) sc[n][lane + 32 * j] = ev[j] * inv;
    }
    __syncwarp();

    // out[m, h] = sum_k attn[n,k] * v_half[b,k,h]  -> stored HALF for tensor-core k_ff
    {
        const __half* __restrict__ vb = d_vh + (size_t)b * L_ * H_;
        const int h = tid * 2;
        const int n = warp;
        float oa = 0.f, ob = 0.f, oc = 0.f, od = 0.f;
        float pa = 0.f, pb = 0.f, pc = 0.f, pd = 0.f;
#pragma unroll 2
        for (int k = 0; k < L_; k += 4) {
            const float a0 = sc[n][k],     a1 = sc[n][k + 1];
            const float a2 = sc[n][k + 2], a3 = sc[n][k + 3];
            __half2 v0 = *reinterpret_cast<const __half2*>(vb + (size_t)k * H_ + h);
            __half2 v1 = *reinterpret_cast<const __half2*>(vb + (size_t)(k + 1) * H_ + h);
            __half2 v2 = *reinterpret_cast<const __half2*>(vb + (size_t)(k + 2) * H_ + h);
            __half2 v3 = *reinterpret_cast<const __half2*>(vb + (size_t)(k + 3) * H_ + h);
            float2 f0 = __half22float2(v0);
            float2 f1 = __half22float2(v1);
            float2 f2 = __half22float2(v2);
            float2 f3 = __half22float2(v3);
            oa += a0 * f0.x; pa += a0 * f0.y;
            ob += a1 * f1.x; pb += a1 * f1.y;
            oc += a2 * f2.x; pc += a2 * f2.y;
            od += a3 * f3.x; pd += a3 * f3.y;
        }
        *reinterpret_cast<__half2*>(d_attnouth + (size_t)m * H_ + h) =
            __floats2half2_rn((oa + ob) + (oc + od), (pa + pb) + (pc + pd));
    }
}

// ---------------- stage 4: output projection, K-split x8 + atomic epilogue ----------------
__global__ void __launch_bounds__(256) k_ff(const float* __restrict__ Wff,
                                            const float* __restrict__ bff,
                                            float* __restrict__ out)
{
    const int c = blockIdx.z;          // K chunk 0..7, 64 each
    hgemm<__half, float, true, float>(d_attnouth + c * 64, H_, Wff + c * 64, H_,
                                      (c == 0) ? bff : nullptr,
                                      out, H_, ML_, H_, 64);
}

// ---------------- launch ----------------
extern "C" void kernel_launch(void* const* d_in, const int* in_sizes, int n_in,
                              void* d_out, int out_size)
{
    (void)n_in; (void)out_size;
    const float* key     = (const float*)d_in[0];
    const float* query   = (const float*)d_in[1];
    const float* value   = (const float*)d_in[2];
    const int*   seq_len = (const int*)d_in[3];
    const int ip = (in_sizes[4] == 1) ? 5 : 4;   // skip lex_num if present
    const int*   pos_s  = (const int*)d_in[ip + 0];
    const int*   pos_e  = (const int*)d_in[ip + 1];
    const float* pe     = (const float*)d_in[ip + 2];
    const float* W_fus  = (const float*)d_in[ip + 3];
    const float* b_fus  = (const float*)d_in[ip + 4];
    const float* Wk     = (const float*)d_in[ip + 5];
    const float* bk     = (const float*)d_in[ip + 6];
    const float* Wq     = (const float*)d_in[ip + 7];
    const float* bq     = (const float*)d_in[ip + 8];
    const float* Wv     = (const float*)d_in[ip + 9];
    const float* bv     = (const float*)d_in[ip + 10];
    const float* Wr     = (const float*)d_in[ip + 11];
    const float* u_bias = (const float*)d_in[ip + 13];
    const float* v_bias = (const float*)d_in[ip + 14];
    const float* Wff    = (const float*)d_in[ip + 15];
    const float* bff    = (const float*)d_in[ip + 16];
    // d_in[ip+12] (br) intentionally unused: constant over k under softmax

    k_pre  <<<dim3(8, 6, 8), 256>>>(key, query, value, Wk, bk, Wq, bq, Wv, bv,
                                    pe, W_fus, b_fus, Wr, u_bias, v_bias);
    k_gqk  <<<dim3(8, 6, 25), 256>>>((float*)d_out);
    k_attn <<<ML_, 256>>>(pos_s, pos_e, seq_len);
    k_ff   <<<dim3(8, 6, 8), 256>>>(Wff, bff, (float*)d_out);
}

// round 13
// speedup vs baseline: 2.4844x; 1.0138x over previous
#include <cuda_runtime.h>
#include <cuda_fp16.h>
#include <cstdint>
#include <cstddef>

#define B_    2
#define L_    192
#define H_    512
#define NH_   8
#define ML_   (B_*L_)     // 384 rows (b,l) flattened
#define TROWS_ 383        // distinct position diffs: [-191, 191]
#define SCP_  196         // padded score row
#define GP_   520         // padded half row (1040B) -> conflict-free ldmatrix

// ---------------- scratch (device globals; no allocation allowed) ----------------
static __device__ __align__(16) __half d_Th[4 * TROWS_ * H_];   // 4 pe tables (T0 includes b_fus)
static __device__ __align__(16) __half d_kh[ML_ * H_];
static __device__ __align__(16) __half d_qkAh[ML_ * H_];        // qproj + bq + u_bias (half)
static __device__ __align__(16) __half d_uh[ML_ * H_];          // qproj + bq + v_bias (half)
static __device__ __align__(16) __half d_vh[ML_ * H_];
static __device__ __align__(16) __half d_gh[ML_ * NH_ * H_];
static __device__ __align__(16) __half d_WrTh[NH_ * H_ * 64];   // Wr transposed per head [h][f][d]
static __device__ __align__(16) float  d_qk[2 * NH_ * L_ * L_];
static __device__ __align__(16) __half d_attnouth[ML_ * H_];

__device__ __forceinline__ float st_conv(float v, float*)  { return v; }
__device__ __forceinline__ __half st_conv(float v, __half*) { return __float2half(v); }

template<class T, class U> struct is_same_t { static const bool v = false; };
template<class T> struct is_same_t<T, T>    { static const bool v = true;  };

// ---------------- tensor-core HGEMM: 64x64 tile, BK=32, mma.m16n8k16 ----------------
// C[m,n] = sum_k A[m,k] * B[n,k]. Tile coords (bxi, byi) passed explicitly.
template<typename AT, typename BT, bool ATOMIC, typename OT>
__device__ __forceinline__ void hgemm(
    int bxi, int byi,
    const AT* __restrict__ A, int lda,
    const BT* __restrict__ B, int ldb,
    const float* __restrict__ bias,
    OT* __restrict__ C, int ldc,
    int M, int N, int K,
    const float* __restrict__ addA = nullptr,
    __half* __restrict__ C2 = nullptr,
    const float* __restrict__ add2 = nullptr)
{
    __shared__ __half As[2][64][40];
    __shared__ __half Bs[2][64][40];
    const int tid  = threadIdx.x;
    const int lane = tid & 31, warp = tid >> 5;
    const int wm = warp >> 1, wn = warp & 1;
    const int m0 = byi * 64, n0 = bxi * 64;

    float acc[4][4];
#pragma unroll
    for (int j = 0; j < 4; ++j)
#pragma unroll
        for (int r = 0; r < 4; ++r) acc[j][r] = 0.f;

    const int rf = tid >> 3, kcf = (tid & 7) * 4;  // fp32 path: rows rf and rf+32
    const int rh = tid >> 2, kch = (tid & 3) * 8;  // half path

    float4 afv0, afv1, bfv0, bfv1; uint4 ahv, bhv;

    auto fetchA = [&](int k0) {
        if constexpr (is_same_t<AT, float>::v) {
            const float* Af = reinterpret_cast<const float*>(A);
            afv0 = make_float4(0.f, 0.f, 0.f, 0.f);
            afv1 = make_float4(0.f, 0.f, 0.f, 0.f);
            if (m0 + rf < M)
                afv0 = *reinterpret_cast<const float4*>(Af + (size_t)(m0 + rf) * lda + k0 + kcf);
            if (m0 + rf + 32 < M)
                afv1 = *reinterpret_cast<const float4*>(Af + (size_t)(m0 + rf + 32) * lda + k0 + kcf);
        } else {
            ahv = make_uint4(0u, 0u, 0u, 0u);
            if (m0 + rh < M)
                ahv = *reinterpret_cast<const uint4*>(
                    reinterpret_cast<const __half*>(A) + (size_t)(m0 + rh) * lda + k0 + kch);
        }
    };
    auto fetchB = [&](int k0) {
        if constexpr (is_same_t<BT, float>::v) {
            const float* Bf = reinterpret_cast<const float*>(B);
            bfv0 = make_float4(0.f, 0.f, 0.f, 0.f);
            bfv1 = make_float4(0.f, 0.f, 0.f, 0.f);
            if (n0 + rf < N)
                bfv0 = *reinterpret_cast<const float4*>(Bf + (size_t)(n0 + rf) * ldb + k0 + kcf);
            if (n0 + rf + 32 < N)
                bfv1 = *reinterpret_cast<const float4*>(Bf + (size_t)(n0 + rf + 32) * ldb + k0 + kcf);
        } else {
            bhv = make_uint4(0u, 0u, 0u, 0u);
            if (n0 + rh < N)
                bhv = *reinterpret_cast<const uint4*>(
                    reinterpret_cast<const __half*>(B) + (size_t)(n0 + rh) * ldb + k0 + kch);
        }
    };
    auto packh = [](const float4& f) {
        __half2 h0 = __floats2half2_rn(f.x, f.y);
        __half2 h1 = __floats2half2_rn(f.z, f.w);
        uint2 u;
        u.x = *reinterpret_cast<unsigned*>(&h0);
        u.y = *reinterpret_cast<unsigned*>(&h1);
        return u;
    };
    auto commitA = [&](int buf) {
        if constexpr (is_same_t<AT, float>::v) {
            *reinterpret_cast<uint2*>(&As[buf][rf][kcf])      = packh(afv0);
            *reinterpret_cast<uint2*>(&As[buf][rf + 32][kcf]) = packh(afv1);
        } else {
            *reinterpret_cast<uint4*>(&As[buf][rh][kch]) = ahv;
        }
    };
    auto commitB = [&](int buf) {
        if constexpr (is_same_t<BT, float>::v) {
            *reinterpret_cast<uint2*>(&Bs[buf][rf][kcf])      = packh(bfv0);
            *reinterpret_cast<uint2*>(&Bs[buf][rf + 32][kcf]) = packh(bfv1);
        } else {
            *reinterpret_cast<uint4*>(&Bs[buf][rh][kch]) = bhv;
        }
    };

    fetchA(0); fetchB(0);
    commitA(0); commitB(0);
    __syncthreads();

    const int fr = lane & 15;
    const int fc = (lane >> 4) << 3;

    int buf = 0;
    for (int k0 = 0; k0 < K; k0 += 32) {
        const bool hn = (k0 + 32 < K);
        if (hn) { fetchA(k0 + 32); fetchB(k0 + 32); }

#pragma unroll
        for (int ks = 0; ks < 2; ++ks) {
            uint32_t a0, a1, a2, a3;
            {
                uint32_t addr = (uint32_t)__cvta_generic_to_shared(
                    &As[buf][wm * 16 + fr][ks * 16 + fc]);
                asm volatile("ldmatrix.sync.aligned.m8n8.x4.shared.b16 {%0,%1,%2,%3}, [%4];"
                             : "=r"(a0), "=r"(a1), "=r"(a2), "=r"(a3) : "r"(addr));
            }
#pragma unroll
            for (int jp = 0; jp < 2; ++jp) {
                uint32_t b0, b1, b2, b3;
                uint32_t addr = (uint32_t)__cvta_generic_to_shared(
                    &Bs[buf][wn * 32 + jp * 16 + fr][ks * 16 + fc]);
                asm volatile("ldmatrix.sync.aligned.m8n8.x4.shared.b16 {%0,%1,%2,%3}, [%4];"
                             : "=r"(b0), "=r"(b1), "=r"(b2), "=r"(b3) : "r"(addr));
                asm volatile("mma.sync.aligned.m16n8k16.row.col.f32.f16.f16.f32 "
                             "{%0,%1,%2,%3}, {%4,%5,%6,%7}, {%8,%9}, {%0,%1,%2,%3};"
                             : "+f"(acc[2 * jp][0]), "+f"(acc[2 * jp][1]),
                               "+f"(acc[2 * jp][2]), "+f"(acc[2 * jp][3])
                             : "r"(a0), "r"(a1), "r"(a2), "r"(a3), "r"(b0), "r"(b2));
                asm volatile("mma.sync.aligned.m16n8k16.row.col.f32.f16.f16.f32 "
                             "{%0,%1,%2,%3}, {%4,%5,%6,%7}, {%8,%9}, {%0,%1,%2,%3};"
                             : "+f"(acc[2 * jp + 1][0]), "+f"(acc[2 * jp + 1][1]),
                               "+f"(acc[2 * jp + 1][2]), "+f"(acc[2 * jp + 1][3])
                             : "r"(a0), "r"(a1), "r"(a2), "r"(a3), "r"(b1), "r"(b3));
            }
        }
        if (hn) { commitA(buf ^ 1); commitB(buf ^ 1); }
        __syncthreads();
        buf ^= 1;
    }

    const int er = lane >> 2;
    const int ec = (lane & 3) * 2;
#pragma unroll
    for (int j = 0; j < 4; ++j) {
        const int colb = n0 + wn * 32 + j * 8 + ec;
#pragma unroll
        for (int rr = 0; rr < 2; ++rr) {
            const int row = m0 + wm * 16 + er + rr * 8;
            if (row < M) {
#pragma unroll
                for (int cc = 0; cc < 2; ++cc) {
                    const int c = colb + cc;
                    if (c < N) {
                        float v = acc[j][rr * 2 + cc];
                        if (bias) v += bias[c];
                        if (ATOMIC) {
                            atomicAdd(reinterpret_cast<float*>(&C[(size_t)row * ldc + c]), v);
                        } else {
                            float v1 = v;
                            if (addA) v1 += addA[c];
                            C[(size_t)row * ldc + c] = st_conv(v1, (OT*)nullptr);
                            if (C2) C2[(size_t)row * ldc + c] = __float2half(v + add2[c]);
                        }
                    }
                }
            }
        }
    }
}

// ---------------- stage 1: projections + pe tables + Wr transpose ----------------
__global__ void __launch_bounds__(256) k_pre(
    const float* __restrict__ key, const float* __restrict__ query, const float* __restrict__ value,
    const float* __restrict__ Wk, const float* __restrict__ bk,
    const float* __restrict__ Wq, const float* __restrict__ bq,
    const float* __restrict__ Wv, const float* __restrict__ bv,
    const float* __restrict__ pe, const float* __restrict__ W_fus,
    const float* __restrict__ b_fus, const float* __restrict__ Wr,
    const float* __restrict__ u_bias, const float* __restrict__ v_bias)
{
    const int z = blockIdx.z;
    const int bx = blockIdx.x, by = blockIdx.y;
    if (z == 0) {
        hgemm<float, float, false, __half>(bx, by, key, H_, Wk, H_, bk, d_kh, H_, ML_, H_, H_);
    } else if (z == 1) {
        hgemm<float, float, false, __half>(bx, by, query, H_, Wq, H_, bq, d_qkAh, H_, ML_, H_, H_,
                                           u_bias, d_uh, v_bias);
    } else if (z == 2) {
        hgemm<float, float, false, __half>(bx, by, value, H_, Wv, H_, bv, d_vh, H_, ML_, H_, H_);
    } else if (z < 7) {
        const int t = z - 3;   // tables 0..3; b_fus folded into T0
        hgemm<float, float, false, __half>(bx, by, pe + 321 * H_, H_, W_fus + t * 256, 2 * H_,
                                           (t == 0) ? b_fus : nullptr,
                                           d_Th + (size_t)t * TROWS_ * H_, H_, TROWS_, H_, 256);
    } else {
        // transpose Wr -> d_WrTh[h][f][d] = Wr[h*64+d][f]   (half)
        const int stride = 48 * 256;
        const int start = (by * 8 + bx) * 256 + threadIdx.x;
        for (int i = start; i < NH_ * H_ * 64; i += stride) {
            const int h = i >> 15;
            const int rem = i & 32767;
            const int f = rem >> 6;
            const int d = rem & 63;
            d_WrTh[i] = __float2half(Wr[(size_t)(h * 64 + d) * H_ + f]);
        }
    }
}

// -------- stage 2: g + per-head qk GEMMs (compact grid) + early zero of d_out --------
__global__ void __launch_bounds__(256) k_gqk(float* __restrict__ out)
{
    const int z = blockIdx.z;
    if (z < 8) {
        hgemm<__half, __half, false, __half>(blockIdx.x, blockIdx.y,
                                             d_uh + z * 64, H_, d_WrTh + (size_t)z * H_ * 64, 64,
                                             nullptr, d_gh + z * H_, NH_ * H_, ML_, H_, 64);
    } else if (z < 11) {
        // qk: 16 combos x 9 tiles = 144 blocks packed into 3 full z-slices
        const int t = (z - 8) * 48 + blockIdx.y * 8 + blockIdx.x;
        if (t >= 144) return;
        const int combo = t / 9, tile = t % 9;
        const int b = combo >> 3, n = combo & 7;
        hgemm<__half, __half, false, float>(tile % 3, tile / 3,
                                            d_qkAh + (size_t)b * L_ * H_ + n * 64, H_,
                                            d_kh   + (size_t)b * L_ * H_ + n * 64, H_, nullptr,
                                            d_qk + (size_t)combo * L_ * L_, L_, L_, L_, 64);
    } else {
        const float4 z4 = make_float4(0.f, 0.f, 0.f, 0.f);
        float4* o4 = reinterpret_cast<float4*>(out);
        const int stride = 48 * 256;
        const int start = (blockIdx.y * 8 + blockIdx.x) * 256 + threadIdx.x;
        for (int i = start; i < (ML_ * H_) / 4; i += stride) o4[i] = z4;
    }
}

// ------ stage 3: fused rel-scores (tensor-core, pipelined) + softmax + attn@V ------
__global__ void __launch_bounds__(256, 3) k_attn(
    const int* __restrict__ pos_s,
    const int* __restrict__ pos_e,
    const int* __restrict__ seq_len)
{
    __shared__ __align__(16) __half g_s[NH_][GP_];
    __shared__ __align__(16) __half R[16][GP_];
    __shared__ __align__(16) float sc[NH_][SCP_];
    __shared__ int ksp[L_], kep[L_];

    const int m = blockIdx.x;          // b*L + q
    const int b = m / L_;
    const int qi = m % L_;
    const int tid = threadIdx.x;
    const int lane = tid & 31;
    const int warp = tid >> 5;

    for (int i = tid; i < (NH_ * H_) / 8; i += 256) {
        const int n = i >> 6;
        const int c = i & 63;
        *reinterpret_cast<uint4*>(&g_s[n][c * 8]) =
            *reinterpret_cast<const uint4*>(d_gh + (size_t)m * (NH_ * H_) + n * H_ + c * 8);
    }
    for (int i = tid; i < NH_ * L_; i += 256) {
        const int n = i / L_, k = i % L_;
        sc[n][k] = d_qk[((size_t)(b * NH_ + n) * L_ + qi) * L_ + k];
    }
    for (int i = tid; i < L_; i += 256) { ksp[i] = pos_s[b * L_ + i]; kep[i] = pos_e[b * L_ + i]; }
    const int psq = pos_s[m], peq = pos_e[m];
    const int slen = seq_len[b];
    __syncthreads();

    const __half2 hz = __float2half2_rn(0.f);
    const __half* __restrict__ T = d_Th;
    const int lane8 = lane << 3;
    const int fr = lane & 15;
    const int fc = (lane >> 4) << 3;
    const int er = lane >> 2;
    const int ec = (lane & 3) * 2;

    uint4 A0, A1, A2, A3, Bq0, Bq1, Bq2, Bq3;
    auto loadKey = [&](int kk) {
        const int o0 = ((0 * TROWS_ + psq - ksp[kk] + 191) << 9);
        const int o1 = ((1 * TROWS_ + psq - kep[kk] + 191) << 9);
        const int o2 = ((2 * TROWS_ + peq - ksp[kk] + 191) << 9);
        const int o3 = ((3 * TROWS_ + peq - kep[kk] + 191) << 9);
        A0  = *reinterpret_cast<const uint4*>(T + o0 + lane8);
        A1  = *reinterpret_cast<const uint4*>(T + o1 + lane8);
        A2  = *reinterpret_cast<const uint4*>(T + o2 + lane8);
        A3  = *reinterpret_cast<const uint4*>(T + o3 + lane8);
        Bq0 = *reinterpret_cast<const uint4*>(T + o0 + lane8 + 256);
        Bq1 = *reinterpret_cast<const uint4*>(T + o1 + lane8 + 256);
        Bq2 = *reinterpret_cast<const uint4*>(T + o2 + lane8 + 256);
        Bq3 = *reinterpret_cast<const uint4*>(T + o3 + lane8 + 256);
    };
    auto reluStore = [&](int kl) {
        {
            const __half2* c0 = reinterpret_cast<const __half2*>(&A0);
            const __half2* c1 = reinterpret_cast<const __half2*>(&A1);
            const __half2* c2 = reinterpret_cast<const __half2*>(&A2);
            const __half2* c3 = reinterpret_cast<const __half2*>(&A3);
            __half2 r[4];
#pragma unroll
            for (int j = 0; j < 4; ++j) {
                __half2 s = __hadd2(__hadd2(c0[j], c1[j]), __hadd2(c2[j], c3[j]));
                r[j] = __hmax2(s, hz);
            }
            *reinterpret_cast<uint4*>(&R[kl][lane8]) = *reinterpret_cast<uint4*>(r);
        }
        {
            const __half2* c0 = reinterpret_cast<const __half2*>(&Bq0);
            const __half2* c1 = reinterpret_cast<const __half2*>(&Bq1);
            const __half2* c2 = reinterpret_cast<const __half2*>(&Bq2);
            const __half2* c3 = reinterpret_cast<const __half2*>(&Bq3);
            __half2 r[4];
#pragma unroll
            for (int j = 0; j < 4; ++j) {
                __half2 s = __hadd2(__hadd2(c0[j], c1[j]), __hadd2(c2[j], c3[j]));
                r[j] = __hmax2(s, hz);
            }
            *reinterpret_cast<uint4*>(&R[kl][256 + lane8]) = *reinterpret_cast<uint4*>(r);
        }
    };

    const int kl0 = warp * 2;
    loadKey(kl0);                      // chunk 0, key e=0
#pragma unroll 1
    for (int ch = 0; ch < 12; ++ch) {
        const int kb = ch * 16;
        reluStore(kl0);                // consume regs (key kb+kl0)
        loadKey(kb + kl0 + 1);         // prefetch e=1
        reluStore(kl0 + 1);
        if (ch < 11) loadKey(kb + 16 + kl0);  // prefetch next chunk's e=0: in flight through Phase B
        __syncthreads();

        // Phase B: scores[16,8] += R @ g^T ; warp owns 4 k-steps
        float acc[4] = {0.f, 0.f, 0.f, 0.f};
#pragma unroll
        for (int ks = 0; ks < 4; ++ks) {
            const int kd = (warp * 4 + ks) * 16;
            uint32_t a0, a1, a2, a3;
            uint32_t addrA = (uint32_t)__cvta_generic_to_shared(&R[fr][kd + fc]);
            asm volatile("ldmatrix.sync.aligned.m8n8.x4.shared.b16 {%0,%1,%2,%3}, [%4];"
                         : "=r"(a0), "=r"(a1), "=r"(a2), "=r"(a3) : "r"(addrA));
            uint32_t b0, b1;
            uint32_t addrB = (uint32_t)__cvta_generic_to_shared(
                &g_s[lane & 7][kd + ((lane >> 3) & 1) * 8]);
            asm volatile("ldmatrix.sync.aligned.m8n8.x2.shared.b16 {%0,%1}, [%2];"
                         : "=r"(b0), "=r"(b1) : "r"(addrB));
            asm volatile("mma.sync.aligned.m16n8k16.row.col.f32.f16.f16.f32 "
                         "{%0,%1,%2,%3}, {%4,%5,%6,%7}, {%8,%9}, {%0,%1,%2,%3};"
                         : "+f"(acc[0]), "+f"(acc[1]), "+f"(acc[2]), "+f"(acc[3])
                         : "r"(a0), "r"(a1), "r"(a2), "r"(a3), "r"(b0), "r"(b1));
        }
        atomicAdd(&sc[ec][kb + er], acc[0]);
        atomicAdd(&sc[ec + 1][kb + er], acc[1]);
        atomicAdd(&sc[ec][kb + er + 8], acc[2]);
        atomicAdd(&sc[ec + 1][kb + er + 8], acc[3]);
        __syncthreads();
    }

    // softmax over k (scale + mask fused), warp = head
    {
        const int n = warp;
        float val[6];
        float mx = -3.4e38f;
#pragma unroll
        for (int j = 0; j < 6; ++j) {
            const int k = lane + 32 * j;
            const float v = sc[n][k] * 0.125f;
            val[j] = (k < slen) ? v : -1e30f;
            mx = fmaxf(mx, val[j]);
        }
#pragma unroll
        for (int s = 16; s > 0; s >>= 1) mx = fmaxf(mx, __shfl_xor_sync(0xffffffffu, mx, s));
        float sum = 0.f;
#pragma unroll
        for (int j = 0; j < 6; ++j) {
            val[j] = __expf(val[j] - mx);
            sum += val[j];
        }
#pragma unroll
        for (int s = 16; s > 0; s >>= 1) sum += __shfl_xor_sync(0xffffffffu, sum, s);
        const float inv = 1.f / sum;
#pragma unroll
        for (int j = 0; j < 6; ++j) sc[n][lane + 32 * j] = val[j] * inv;
    }
    __syncwarp();

    // out[m, h] = sum_k attn[n,k] * v_half[b,k,h]  -> stored HALF for tensor-core k_ff
    {
        const __half* __restrict__ vb = d_vh + (size_t)b * L_ * H_;
        const int h = tid * 2;
        const int n = warp;
        float oa = 0.f, ob = 0.f, oc = 0.f, od = 0.f;
        float pa = 0.f, pb = 0.f, pc = 0.f, pd = 0.f;
#pragma unroll 2
        for (int k = 0; k < L_; k += 4) {
            const float a0 = sc[n][k],     a1 = sc[n][k + 1];
            const float a2 = sc[n][k + 2], a3 = sc[n][k + 3];
            __half2 v0 = *reinterpret_cast<const __half2*>(vb + (size_t)k * H_ + h);
            __half2 v1 = *reinterpret_cast<const __half2*>(vb + (size_t)(k + 1) * H_ + h);
            __half2 v2 = *reinterpret_cast<const __half2*>(vb + (size_t)(k + 2) * H_ + h);
            __half2 v3 = *reinterpret_cast<const __half2*>(vb + (size_t)(k + 3) * H_ + h);
            float2 f0 = __half22float2(v0);
            float2 f1 = __half22float2(v1);
            float2 f2 = __half22float2(v2);
            float2 f3 = __half22float2(v3);
            oa += a0 * f0.x; pa += a0 * f0.y;
            ob += a1 * f1.x; pb += a1 * f1.y;
            oc += a2 * f2.x; pc += a2 * f2.y;
            od += a3 * f3.x; pd += a3 * f3.y;
        }
        *reinterpret_cast<__half2*>(d_attnouth + (size_t)m * H_ + h) =
            __floats2half2_rn((oa + ob) + (oc + od), (pa + pb) + (pc + pd));
    }
}

// ---------------- stage 4: output projection, K-split x8 + atomic epilogue ----------------
__global__ void __launch_bounds__(256) k_ff(const float* __restrict__ Wff,
                                            const float* __restrict__ bff,
                                            float* __restrict__ out)
{
    const int c = blockIdx.z;          // K chunk 0..7, 64 each
    hgemm<__half, float, true, float>(blockIdx.x, blockIdx.y,
                                      d_attnouth + c * 64, H_, Wff + c * 64, H_,
                                      (c == 0) ? bff : nullptr,
                                      out, H_, ML_, H_, 64);
}

// ---------------- launch ----------------
extern "C" void kernel_launch(void* const* d_in, const int* in_sizes, int n_in,
                              void* d_out, int out_size)
{
    (void)n_in; (void)out_size;
    const float* key     = (const float*)d_in[0];
    const float* query   = (const float*)d_in[1];
    const float* value   = (const float*)d_in[2];
    const int*   seq_len = (const int*)d_in[3];
    const int ip = (in_sizes[4] == 1) ? 5 : 4;   // skip lex_num if present
    const int*   pos_s  = (const int*)d_in[ip + 0];
    const int*   pos_e  = (const int*)d_in[ip + 1];
    const float* pe     = (const float*)d_in[ip + 2];
    const float* W_fus  = (const float*)d_in[ip + 3];
    const float* b_fus  = (const float*)d_in[ip + 4];
    const float* Wk     = (const float*)d_in[ip + 5];
    const float* bk     = (const float*)d_in[ip + 6];
    const float* Wq     = (const float*)d_in[ip + 7];
    const float* bq     = (const float*)d_in[ip + 8];
    const float* Wv     = (const float*)d_in[ip + 9];
    const float* bv     = (const float*)d_in[ip + 10];
    const float* Wr     = (const float*)d_in[ip + 11];
    const float* u_bias = (const float*)d_in[ip + 13];
    const float* v_bias = (const float*)d_in[ip + 14];
    const float* Wff    = (const float*)d_in[ip + 15];
    const float* bff    = (const float*)d_in[ip + 16];
    // d_in[ip+12] (br) intentionally unused: constant over k under softmax

    k_pre  <<<dim3(8, 6, 8), 256>>>(key, query, value, Wk, bk, Wq, bq, Wv, bv,
                                    pe, W_fus, b_fus, Wr, u_bias, v_bias);
    k_gqk  <<<dim3(8, 6, 12), 256>>>((float*)d_out);
    k_attn <<<ML_, 256>>>(pos_s, pos_e, seq_len);
    k_ff   <<<dim3(8, 6, 8), 256>>>(Wff, bff, (float*)d_out);
}

// round 14
// speedup vs baseline: 2.6384x; 1.0620x over previous
#include <cuda_runtime.h>
#include <cuda_fp16.h>
#include <cuda_fp8.h>
#include <cstdint>
#include <cstddef>

#define B_    2
#define L_    192
#define H_    512
#define NH_   8
#define ML_   (B_*L_)     // 384 rows (b,l) flattened
#define TROWS_ 383        // distinct position diffs: [-191, 191]
#define SCP_  196         // padded score row
#define GP_   520         // padded half row (1040B) -> conflict-free ldmatrix

// ---------------- scratch (device globals; no allocation allowed) ----------------
static __device__ __align__(16) __nv_fp8_e4m3 d_T8[4 * TROWS_ * H_]; // tables x64, fp8 (T0 incl b_fus)
static __device__ __align__(16) __half d_kh[ML_ * H_];
static __device__ __align__(16) __half d_qkAh[ML_ * H_];        // qproj + bq + u_bias (half)
static __device__ __align__(16) __half d_uh[ML_ * H_];          // qproj + bq + v_bias (half)
static __device__ __align__(16) __half d_vh[ML_ * H_];
static __device__ __align__(16) __half d_gh[ML_ * NH_ * H_];
static __device__ __align__(16) __half d_WrTh[NH_ * H_ * 64];   // Wr transposed per head [h][f][d]
static __device__ __align__(16) float  d_qk[2 * NH_ * L_ * L_];
static __device__ __align__(16) __half d_attnouth[ML_ * H_];

__device__ __forceinline__ float st_conv(float v, float*)  { return v; }
__device__ __forceinline__ __half st_conv(float v, __half*) { return __float2half(v); }
__device__ __forceinline__ __nv_fp8_e4m3 st_conv(float v, __nv_fp8_e4m3*) {
    return __nv_fp8_e4m3(v * 64.f);    // x64: relu(64x)=64relu(x); undone in Phase B
}

template<class T, class U> struct is_same_t { static const bool v = false; };
template<class T> struct is_same_t<T, T>    { static const bool v = true;  };

// ---------------- tensor-core HGEMM: 64x64 tile, BK=32, mma.m16n8k16 ----------------
template<typename AT, typename BT, bool ATOMIC, typename OT>
__device__ __forceinline__ void hgemm(
    int bxi, int byi,
    const AT* __restrict__ A, int lda,
    const BT* __restrict__ B, int ldb,
    const float* __restrict__ bias,
    OT* __restrict__ C, int ldc,
    int M, int N, int K,
    const float* __restrict__ addA = nullptr,
    __half* __restrict__ C2 = nullptr,
    const float* __restrict__ add2 = nullptr)
{
    __shared__ __half As[2][64][40];
    __shared__ __half Bs[2][64][40];
    const int tid  = threadIdx.x;
    const int lane = tid & 31, warp = tid >> 5;
    const int wm = warp >> 1, wn = warp & 1;
    const int m0 = byi * 64, n0 = bxi * 64;

    float acc[4][4];
#pragma unroll
    for (int j = 0; j < 4; ++j)
#pragma unroll
        for (int r = 0; r < 4; ++r) acc[j][r] = 0.f;

    const int rf = tid >> 3, kcf = (tid & 7) * 4;
    const int rh = tid >> 2, kch = (tid & 3) * 8;

    float4 afv0, afv1, bfv0, bfv1; uint4 ahv, bhv;

    auto fetchA = [&](int k0) {
        if constexpr (is_same_t<AT, float>::v) {
            const float* Af = reinterpret_cast<const float*>(A);
            afv0 = make_float4(0.f, 0.f, 0.f, 0.f);
            afv1 = make_float4(0.f, 0.f, 0.f, 0.f);
            if (m0 + rf < M)
                afv0 = *reinterpret_cast<const float4*>(Af + (size_t)(m0 + rf) * lda + k0 + kcf);
            if (m0 + rf + 32 < M)
                afv1 = *reinterpret_cast<const float4*>(Af + (size_t)(m0 + rf + 32) * lda + k0 + kcf);
        } else {
            ahv = make_uint4(0u, 0u, 0u, 0u);
            if (m0 + rh < M)
                ahv = *reinterpret_cast<const uint4*>(
                    reinterpret_cast<const __half*>(A) + (size_t)(m0 + rh) * lda + k0 + kch);
        }
    };
    auto fetchB = [&](int k0) {
        if constexpr (is_same_t<BT, float>::v) {
            const float* Bf = reinterpret_cast<const float*>(B);
            bfv0 = make_float4(0.f, 0.f, 0.f, 0.f);
            bfv1 = make_float4(0.f, 0.f, 0.f, 0.f);
            if (n0 + rf < N)
                bfv0 = *reinterpret_cast<const float4*>(Bf + (size_t)(n0 + rf) * ldb + k0 + kcf);
            if (n0 + rf + 32 < N)
                bfv1 = *reinterpret_cast<const float4*>(Bf + (size_t)(n0 + rf + 32) * ldb + k0 + kcf);
        } else {
            bhv = make_uint4(0u, 0u, 0u, 0u);
            if (n0 + rh < N)
                bhv = *reinterpret_cast<const uint4*>(
                    reinterpret_cast<const __half*>(B) + (size_t)(n0 + rh) * ldb + k0 + kch);
        }
    };
    auto packh = [](const float4& f) {
        __half2 h0 = __floats2half2_rn(f.x, f.y);
        __half2 h1 = __floats2half2_rn(f.z, f.w);
        uint2 u;
        u.x = *reinterpret_cast<unsigned*>(&h0);
        u.y = *reinterpret_cast<unsigned*>(&h1);
        return u;
    };
    auto commitA = [&](int buf) {
        if constexpr (is_same_t<AT, float>::v) {
            *reinterpret_cast<uint2*>(&As[buf][rf][kcf])      = packh(afv0);
            *reinterpret_cast<uint2*>(&As[buf][rf + 32][kcf]) = packh(afv1);
        } else {
            *reinterpret_cast<uint4*>(&As[buf][rh][kch]) = ahv;
        }
    };
    auto commitB = [&](int buf) {
        if constexpr (is_same_t<BT, float>::v) {
            *reinterpret_cast<uint2*>(&Bs[buf][rf][kcf])      = packh(bfv0);
            *reinterpret_cast<uint2*>(&Bs[buf][rf + 32][kcf]) = packh(bfv1);
        } else {
            *reinterpret_cast<uint4*>(&Bs[buf][rh][kch]) = bhv;
        }
    };

    fetchA(0); fetchB(0);
    commitA(0); commitB(0);
    __syncthreads();

    const int fr = lane & 15;
    const int fc = (lane >> 4) << 3;

    int buf = 0;
    for (int k0 = 0; k0 < K; k0 += 32) {
        const bool hn = (k0 + 32 < K);
        if (hn) { fetchA(k0 + 32); fetchB(k0 + 32); }

#pragma unroll
        for (int ks = 0; ks < 2; ++ks) {
            uint32_t a0, a1, a2, a3;
            {
                uint32_t addr = (uint32_t)__cvta_generic_to_shared(
                    &As[buf][wm * 16 + fr][ks * 16 + fc]);
                asm volatile("ldmatrix.sync.aligned.m8n8.x4.shared.b16 {%0,%1,%2,%3}, [%4];"
                             : "=r"(a0), "=r"(a1), "=r"(a2), "=r"(a3) : "r"(addr));
            }
#pragma unroll
            for (int jp = 0; jp < 2; ++jp) {
                uint32_t b0, b1, b2, b3;
                uint32_t addr = (uint32_t)__cvta_generic_to_shared(
                    &Bs[buf][wn * 32 + jp * 16 + fr][ks * 16 + fc]);
                asm volatile("ldmatrix.sync.aligned.m8n8.x4.shared.b16 {%0,%1,%2,%3}, [%4];"
                             : "=r"(b0), "=r"(b1), "=r"(b2), "=r"(b3) : "r"(addr));
                asm volatile("mma.sync.aligned.m16n8k16.row.col.f32.f16.f16.f32 "
                             "{%0,%1,%2,%3}, {%4,%5,%6,%7}, {%8,%9}, {%0,%1,%2,%3};"
                             : "+f"(acc[2 * jp][0]), "+f"(acc[2 * jp][1]),
                               "+f"(acc[2 * jp][2]), "+f"(acc[2 * jp][3])
                             : "r"(a0), "r"(a1), "r"(a2), "r"(a3), "r"(b0), "r"(b2));
                asm volatile("mma.sync.aligned.m16n8k16.row.col.f32.f16.f16.f32 "
                             "{%0,%1,%2,%3}, {%4,%5,%6,%7}, {%8,%9}, {%0,%1,%2,%3};"
                             : "+f"(acc[2 * jp + 1][0]), "+f"(acc[2 * jp + 1][1]),
                               "+f"(acc[2 * jp + 1][2]), "+f"(acc[2 * jp + 1][3])
                             : "r"(a0), "r"(a1), "r"(a2), "r"(a3), "r"(b1), "r"(b3));
            }
        }
        if (hn) { commitA(buf ^ 1); commitB(buf ^ 1); }
        __syncthreads();
        buf ^= 1;
    }

    const int er = lane >> 2;
    const int ec = (lane & 3) * 2;
#pragma unroll
    for (int j = 0; j < 4; ++j) {
        const int colb = n0 + wn * 32 + j * 8 + ec;
#pragma unroll
        for (int rr = 0; rr < 2; ++rr) {
            const int row = m0 + wm * 16 + er + rr * 8;
            if (row < M) {
#pragma unroll
                for (int cc = 0; cc < 2; ++cc) {
                    const int c = colb + cc;
                    if (c < N) {
                        float v = acc[j][rr * 2 + cc];
                        if (bias) v += bias[c];
                        if (ATOMIC) {
                            atomicAdd(reinterpret_cast<float*>(&C[(size_t)row * ldc + c]), v);
                        } else {
                            float v1 = v;
                            if (addA) v1 += addA[c];
                            C[(size_t)row * ldc + c] = st_conv(v1, (OT*)nullptr);
                            if (C2) C2[(size_t)row * ldc + c] = __float2half(v + add2[c]);
                        }
                    }
                }
            }
        }
    }
}

// ---------------- stage 1: projections + pe tables (fp8 x64) + Wr transpose ----------------
__global__ void __launch_bounds__(256) k_pre(
    const float* __restrict__ key, const float* __restrict__ query, const float* __restrict__ value,
    const float* __restrict__ Wk, const float* __restrict__ bk,
    const float* __restrict__ Wq, const float* __restrict__ bq,
    const float* __restrict__ Wv, const float* __restrict__ bv,
    const float* __restrict__ pe, const float* __restrict__ W_fus,
    const float* __restrict__ b_fus, const float* __restrict__ Wr,
    const float* __restrict__ u_bias, const float* __restrict__ v_bias)
{
    const int z = blockIdx.z;
    const int bx = blockIdx.x, by = blockIdx.y;
    if (z == 0) {
        hgemm<float, float, false, __half>(bx, by, key, H_, Wk, H_, bk, d_kh, H_, ML_, H_, H_);
    } else if (z == 1) {
        hgemm<float, float, false, __half>(bx, by, query, H_, Wq, H_, bq, d_qkAh, H_, ML_, H_, H_,
                                           u_bias, d_uh, v_bias);
    } else if (z == 2) {
        hgemm<float, float, false, __half>(bx, by, value, H_, Wv, H_, bv, d_vh, H_, ML_, H_, H_);
    } else if (z < 7) {
        const int t = z - 3;   // tables 0..3; b_fus folded into T0; stored fp8 x64
        hgemm<float, float, false, __nv_fp8_e4m3>(bx, by, pe + 321 * H_, H_, W_fus + t * 256, 2 * H_,
                                                  (t == 0) ? b_fus : nullptr,
                                                  d_T8 + (size_t)t * TROWS_ * H_, H_, TROWS_, H_, 256);
    } else {
        const int stride = 48 * 256;
        const int start = (by * 8 + bx) * 256 + threadIdx.x;
        for (int i = start; i < NH_ * H_ * 64; i += stride) {
            const int h = i >> 15;
            const int rem = i & 32767;
            const int f = rem >> 6;
            const int d = rem & 63;
            d_WrTh[i] = __float2half(Wr[(size_t)(h * 64 + d) * H_ + f]);
        }
    }
}

// -------- stage 2: g + per-head qk GEMMs (compact grid) + early zero of d_out --------
__global__ void __launch_bounds__(256) k_gqk(float* __restrict__ out)
{
    const int z = blockIdx.z;
    if (z < 8) {
        hgemm<__half, __half, false, __half>(blockIdx.x, blockIdx.y,
                                             d_uh + z * 64, H_, d_WrTh + (size_t)z * H_ * 64, 64,
                                             nullptr, d_gh + z * H_, NH_ * H_, ML_, H_, 64);
    } else if (z < 11) {
        const int t = (z - 8) * 48 + blockIdx.y * 8 + blockIdx.x;
        if (t >= 144) return;
        const int combo = t / 9, tile = t % 9;
        const int b = combo >> 3, n = combo & 7;
        hgemm<__half, __half, false, float>(tile % 3, tile / 3,
                                            d_qkAh + (size_t)b * L_ * H_ + n * 64, H_,
                                            d_kh   + (size_t)b * L_ * H_ + n * 64, H_, nullptr,
                                            d_qk + (size_t)combo * L_ * L_, L_, L_, L_, 64);
    } else {
        const float4 z4 = make_float4(0.f, 0.f, 0.f, 0.f);
        float4* o4 = reinterpret_cast<float4*>(out);
        const int stride = 48 * 256;
        const int start = (blockIdx.y * 8 + blockIdx.x) * 256 + threadIdx.x;
        for (int i = start; i < (ML_ * H_) / 4; i += stride) o4[i] = z4;
    }
}

// 16 fp8 (uint4) -> 8 half2
__device__ __forceinline__ void cvt_fp8x16(const uint4& v, __half2* out) {
    const uint32_t w[4] = {v.x, v.y, v.z, v.w};
#pragma unroll
    for (int i = 0; i < 4; ++i) {
        unsigned short lo = (unsigned short)(w[i] & 0xffffu);
        unsigned short hi = (unsigned short)(w[i] >> 16);
        uint32_t r0, r1;
        asm("cvt.rn.f16x2.e4m3x2 %0, %1;" : "=r"(r0) : "h"(lo));
        asm("cvt.rn.f16x2.e4m3x2 %0, %1;" : "=r"(r1) : "h"(hi));
        out[2 * i]     = *reinterpret_cast<__half2*>(&r0);
        out[2 * i + 1] = *reinterpret_cast<__half2*>(&r1);
    }
}

// ------ stage 3: fused rel-scores (tensor-core, fp8 tables) + softmax + attn@V ------
__global__ void __launch_bounds__(256, 3) k_attn(
    const int* __restrict__ pos_s,
    const int* __restrict__ pos_e,
    const int* __restrict__ seq_len)
{
    __shared__ __align__(16) __half g_s[NH_][GP_];
    __shared__ __align__(16) __half R[16][GP_];
    __shared__ __align__(16) float sc[NH_][SCP_];
    __shared__ int ksp[L_], kep[L_];

    const int m = blockIdx.x;          // b*L + q
    const int b = m / L_;
    const int qi = m % L_;
    const int tid = threadIdx.x;
    const int lane = tid & 31;
    const int warp = tid >> 5;

    for (int i = tid; i < (NH_ * H_) / 8; i += 256) {
        const int n = i >> 6;
        const int c = i & 63;
        *reinterpret_cast<uint4*>(&g_s[n][c * 8]) =
            *reinterpret_cast<const uint4*>(d_gh + (size_t)m * (NH_ * H_) + n * H_ + c * 8);
    }
    for (int i = tid; i < NH_ * L_; i += 256) {
        const int n = i / L_, k = i % L_;
        sc[n][k] = d_qk[((size_t)(b * NH_ + n) * L_ + qi) * L_ + k];
    }
    for (int i = tid; i < L_; i += 256) { ksp[i] = pos_s[b * L_ + i]; kep[i] = pos_e[b * L_ + i]; }
    const int psq = pos_s[m], peq = pos_e[m];
    const int slen = seq_len[b];
    __syncthreads();

    const __half2 hz = __float2half2_rn(0.f);
    const uint8_t* __restrict__ T8 = reinterpret_cast<const uint8_t*>(d_T8);
    const int lane16 = lane << 4;      // this lane's 16 dims (1 byte each)
    const int fr = lane & 15;
    const int fc = (lane >> 4) << 3;
    const int er = lane >> 2;
    const int ec = (lane & 3) * 2;
    const int nch = (slen + 15) >> 4;  // chunks with at least one live key

    uint4 A0, A1, A2, A3;
    auto loadKey = [&](int kk) {
        A0 = *reinterpret_cast<const uint4*>(T8 + (size_t)((0 * TROWS_ + psq - ksp[kk] + 191) << 9) + lane16);
        A1 = *reinterpret_cast<const uint4*>(T8 + (size_t)((1 * TROWS_ + psq - kep[kk] + 191) << 9) + lane16);
        A2 = *reinterpret_cast<const uint4*>(T8 + (size_t)((2 * TROWS_ + peq - ksp[kk] + 191) << 9) + lane16);
        A3 = *reinterpret_cast<const uint4*>(T8 + (size_t)((3 * TROWS_ + peq - kep[kk] + 191) << 9) + lane16);
    };
    auto reluStore = [&](int kl) {
        __half2 t0[8], t1[8], t2[8], t3[8];
        cvt_fp8x16(A0, t0); cvt_fp8x16(A1, t1);
        cvt_fp8x16(A2, t2); cvt_fp8x16(A3, t3);
        __half2 r[8];
#pragma unroll
        for (int j = 0; j < 8; ++j) {
            __half2 s = __hadd2(__hadd2(t0[j], t1[j]), __hadd2(t2[j], t3[j]));
            r[j] = __hmax2(s, hz);
        }
        *reinterpret_cast<uint4*>(&R[kl][lane16])     = *reinterpret_cast<uint4*>(&r[0]);
        *reinterpret_cast<uint4*>(&R[kl][lane16 + 8]) = *reinterpret_cast<uint4*>(&r[4]);
    };

    const int kl0 = warp * 2;
    loadKey(kl0);
#pragma unroll 1
    for (int ch = 0; ch < nch; ++ch) {
        const int kb = ch * 16;
        reluStore(kl0);
        loadKey(kb + kl0 + 1);
        reluStore(kl0 + 1);
        if (ch + 1 < nch) loadKey(kb + 16 + kl0);   // prefetch next chunk through Phase B
        __syncthreads();

        // Phase B: scores[16,8] += (R @ g^T) / 64 ; warp owns 4 k-steps
        float acc[4] = {0.f, 0.f, 0.f, 0.f};
#pragma unroll
        for (int ks = 0; ks < 4; ++ks) {
            const int kd = (warp * 4 + ks) * 16;
            uint32_t a0, a1, a2, a3;
            uint32_t addrA = (uint32_t)__cvta_generic_to_shared(&R[fr][kd + fc]);
            asm volatile("ldmatrix.sync.aligned.m8n8.x4.shared.b16 {%0,%1,%2,%3}, [%4];"
                         : "=r"(a0), "=r"(a1), "=r"(a2), "=r"(a3) : "r"(addrA));
            uint32_t b0, b1;
            uint32_t addrB = (uint32_t)__cvta_generic_to_shared(
                &g_s[lane & 7][kd + ((lane >> 3) & 1) * 8]);
            asm volatile("ldmatrix.sync.aligned.m8n8.x2.shared.b16 {%0,%1}, [%2];"
                         : "=r"(b0), "=r"(b1) : "r"(addrB));
            asm volatile("mma.sync.aligned.m16n8k16.row.col.f32.f16.f16.f32 "
                         "{%0,%1,%2,%3}, {%4,%5,%6,%7}, {%8,%9}, {%0,%1,%2,%3};"
                         : "+f"(acc[0]), "+f"(acc[1]), "+f"(acc[2]), "+f"(acc[3])
                         : "r"(a0), "r"(a1), "r"(a2), "r"(a3), "r"(b0), "r"(b1));
        }
        const float is = 1.f / 64.f;   // undo fp8 table x64
        atomicAdd(&sc[ec][kb + er], acc[0] * is);
        atomicAdd(&sc[ec + 1][kb + er], acc[1] * is);
        atomicAdd(&sc[ec][kb + er + 8], acc[2] * is);
        atomicAdd(&sc[ec + 1][kb + er + 8], acc[3] * is);
        __syncthreads();
    }

    // softmax over k (scale + mask fused), warp = head
    {
        const int n = warp;
        float val[6];
        float mx = -3.4e38f;
#pragma unroll
        for (int j = 0; j < 6; ++j) {
            const int k = lane + 32 * j;
            const float v = sc[n][k] * 0.125f;
            val[j] = (k < slen) ? v : -1e30f;
            mx = fmaxf(mx, val[j]);
        }
#pragma unroll
        for (int s = 16; s > 0; s >>= 1) mx = fmaxf(mx, __shfl_xor_sync(0xffffffffu, mx, s));
        float sum = 0.f;
#pragma unroll
        for (int j = 0; j < 6; ++j) {
            val[j] = __expf(val[j] - mx);
            sum += val[j];
        }
#pragma unroll
        for (int s = 16; s > 0; s >>= 1) sum += __shfl_xor_sync(0xffffffffu, sum, s);
        const float inv = 1.f / sum;
#pragma unroll
        for (int j = 0; j < 6; ++j) sc[n][lane + 32 * j] = val[j] * inv;
    }
    __syncwarp();

    // out[m, h] = sum_{k<slen} attn[n,k] * v_half[b,k,h]  (weights beyond slen are exactly 0)
    {
        const __half* __restrict__ vb = d_vh + (size_t)b * L_ * H_;
        const int h = tid * 2;
        const int n = warp;
        const int kmax = (slen + 3) & ~3;
        float oa = 0.f, ob = 0.f, oc = 0.f, od = 0.f;
        float pa = 0.f, pb = 0.f, pc = 0.f, pd = 0.f;
#pragma unroll 2
        for (int k = 0; k < kmax; k += 4) {
            const float a0 = sc[n][k],     a1 = sc[n][k + 1];
            const float a2 = sc[n][k + 2], a3 = sc[n][k + 3];
            __half2 v0 = *reinterpret_cast<const __half2*>(vb + (size_t)k * H_ + h);
            __half2 v1 = *reinterpret_cast<const __half2*>(vb + (size_t)(k + 1) * H_ + h);
            __half2 v2 = *reinterpret_cast<const __half2*>(vb + (size_t)(k + 2) * H_ + h);
            __half2 v3 = *reinterpret_cast<const __half2*>(vb + (size_t)(k + 3) * H_ + h);
            float2 f0 = __half22float2(v0);
            float2 f1 = __half22float2(v1);
            float2 f2 = __half22float2(v2);
            float2 f3 = __half22float2(v3);
            oa += a0 * f0.x; pa += a0 * f0.y;
            ob += a1 * f1.x; pb += a1 * f1.y;
            oc += a2 * f2.x; pc += a2 * f2.y;
            od += a3 * f3.x; pd += a3 * f3.y;
        }
        *reinterpret_cast<__half2*>(d_attnouth + (size_t)m * H_ + h) =
            __floats2half2_rn((oa + ob) + (oc + od), (pa + pb) + (pc + pd));
    }
}

// ---------------- stage 4: output projection, K-split x8 + atomic epilogue ----------------
__global__ void __launch_bounds__(256) k_ff(const float* __restrict__ Wff,
                                            const float* __restrict__ bff,
                                            float* __restrict__ out)
{
    const int c = blockIdx.z;
    hgemm<__half, float, true, float>(blockIdx.x, blockIdx.y,
                                      d_attnouth + c * 64, H_, Wff + c * 64, H_,
                                      (c == 0) ? bff : nullptr,
                                      out, H_, ML_, H_, 64);
}

// ---------------- launch ----------------
extern "C" void kernel_launch(void* const* d_in, const int* in_sizes, int n_in,
                              void* d_out, int out_size)
{
    (void)n_in; (void)out_size;
    const float* key     = (const float*)d_in[0];
    const float* query   = (const float*)d_in[1];
    const float* value   = (const float*)d_in[2];
    const int*   seq_len = (const int*)d_in[3];
    const int ip = (in_sizes[4] == 1) ? 5 : 4;   // skip lex_num if present
    const int*   pos_s  = (const int*)d_in[ip + 0];
    const int*   pos_e  = (const int*)d_in[ip + 1];
    const float* pe     = (const float*)d_in[ip + 2];
    const float* W_fus  = (const float*)d_in[ip + 3];
    const float* b_fus  = (const float*)d_in[ip + 4];
    const float* Wk     = (const float*)d_in[ip + 5];
    const float* bk     = (const float*)d_in[ip + 6];
    const float* Wq     = (const float*)d_in[ip + 7];
    const float* bq     = (const float*)d_in[ip + 8];
    const float* Wv     = (const float*)d_in[ip + 9];
    const float* bv     = (const float*)d_in[ip + 10];
    const float* Wr     = (const float*)d_in[ip + 11];
    const float* u_bias = (const float*)d_in[ip + 13];
    const float* v_bias = (const float*)d_in[ip + 14];
    const float* Wff    = (const float*)d_in[ip + 15];
    const float* bff    = (const float*)d_in[ip + 16];
    // d_in[ip+12] (br) intentionally unused: constant over k under softmax

    k_pre  <<<dim3(8, 6, 8), 256>>>(key, query, value, Wk, bk, Wq, bq, Wv, bv,
                                    pe, W_fus, b_fus, Wr, u_bias, v_bias);
    k_gqk  <<<dim3(8, 6, 12), 256>>>((float*)d_out);
    k_attn <<<ML_, 256>>>(pos_s, pos_e, seq_len);
    k_ff   <<<dim3(8, 6, 8), 256>>>(Wff, bff, (float*)d_out);
}

// round 15
// speedup vs baseline: 2.6500x; 1.0044x over previous
#include <cuda_runtime.h>
#include <cuda_fp16.h>
#include <cuda_fp8.h>
#include <cstdint>
#include <cstddef>

#define B_    2
#define L_    192
#define H_    512
#define NH_   8
#define ML_   (B_*L_)     // 384 rows (b,l) flattened
#define TROWS_ 383        // distinct position diffs: [-191, 191]
#define SCP_  196         // padded score row
#define GP_   520         // padded half row (1040B) -> conflict-free ldmatrix

// ---------------- scratch (device globals; no allocation allowed) ----------------
static __device__ __align__(16) __nv_fp8_e4m3 d_T8[4 * TROWS_ * H_]; // tables x64, fp8 (T0 incl b_fus)
static __device__ __align__(16) __half d_kh[ML_ * H_];
static __device__ __align__(16) __half d_qkAh[ML_ * H_];        // qproj + bq + u_bias (half)
static __device__ __align__(16) __half d_uh[ML_ * H_];          // qproj + bq + v_bias (half)
static __device__ __align__(16) __half d_vh[ML_ * H_];
static __device__ __align__(16) __half d_gh[ML_ * NH_ * H_];
static __device__ __align__(16) __half d_WrTh[NH_ * H_ * 64];   // Wr transposed per head [h][f][d]
static __device__ __align__(16) float  d_qk[2 * NH_ * L_ * L_];
static __device__ __align__(16) __half d_attnouth[ML_ * H_];

__device__ __forceinline__ float st_conv(float v, float*)  { return v; }
__device__ __forceinline__ __half st_conv(float v, __half*) { return __float2half(v); }
__device__ __forceinline__ __nv_fp8_e4m3 st_conv(float v, __nv_fp8_e4m3*) {
    return __nv_fp8_e4m3(v * 64.f);    // x64: relu(64x)=64relu(x); undone in Phase B
}

template<class T, class U> struct is_same_t { static const bool v = false; };
template<class T> struct is_same_t<T, T>    { static const bool v = true;  };

__device__ __forceinline__ void cp16(uint32_t saddr, const void* g, int bytes) {
    asm volatile("cp.async.cg.shared.global [%0], [%1], 16, %2;"
                 :: "r"(saddr), "l"(g), "r"(bytes));
}
__device__ __forceinline__ void cp_commit() { asm volatile("cp.async.commit_group;"); }
__device__ __forceinline__ void cp_wait0()  { asm volatile("cp.async.wait_group 0;"); }

// ---------------- tensor-core HGEMM: 64x64 tile, BK=32, mma.m16n8k16 ----------------
// half sources use cp.async straight into smem; fp32 sources stage in regs + convert.
template<typename AT, typename BT, bool ATOMIC, typename OT>
__device__ __forceinline__ void hgemm(
    int bxi, int byi,
    const AT* __restrict__ A, int lda,
    const BT* __restrict__ B, int ldb,
    const float* __restrict__ bias,
    OT* __restrict__ C, int ldc,
    int M, int N, int K,
    const float* __restrict__ addA = nullptr,
    __half* __restrict__ C2 = nullptr,
    const float* __restrict__ add2 = nullptr)
{
    __shared__ __half As[2][64][40];
    __shared__ __half Bs[2][64][40];
    const int tid  = threadIdx.x;
    const int lane = tid & 31, warp = tid >> 5;
    const int wm = warp >> 1, wn = warp & 1;
    const int m0 = byi * 64, n0 = bxi * 64;

    float acc[4][4];
#pragma unroll
    for (int j = 0; j < 4; ++j)
#pragma unroll
        for (int r = 0; r < 4; ++r) acc[j][r] = 0.f;

    const int rf = tid >> 3, kcf = (tid & 7) * 4;
    const int rh = tid >> 2, kch = (tid & 3) * 8;

    float4 afv0, afv1, bfv0, bfv1;

    // fetch: fp32 -> regs; half -> cp.async into smem[buf]
    auto fetchA = [&](int k0, int buf) {
        if constexpr (is_same_t<AT, float>::v) {
            const float* Af = reinterpret_cast<const float*>(A);
            afv0 = make_float4(0.f, 0.f, 0.f, 0.f);
            afv1 = make_float4(0.f, 0.f, 0.f, 0.f);
            if (m0 + rf < M)
                afv0 = *reinterpret_cast<const float4*>(Af + (size_t)(m0 + rf) * lda + k0 + kcf);
            if (m0 + rf + 32 < M)
                afv1 = *reinterpret_cast<const float4*>(Af + (size_t)(m0 + rf + 32) * lda + k0 + kcf);
        } else {
            const __half* Ah = reinterpret_cast<const __half*>(A);
            cp16((uint32_t)__cvta_generic_to_shared(&As[buf][rh][kch]),
                 Ah + (size_t)(m0 + rh) * lda + k0 + kch,
                 (m0 + rh < M) ? 16 : 0);
        }
    };
    auto fetchB = [&](int k0, int buf) {
        if constexpr (is_same_t<BT, float>::v) {
            const float* Bf = reinterpret_cast<const float*>(B);
            bfv0 = make_float4(0.f, 0.f, 0.f, 0.f);
            bfv1 = make_float4(0.f, 0.f, 0.f, 0.f);
            if (n0 + rf < N)
                bfv0 = *reinterpret_cast<const float4*>(Bf + (size_t)(n0 + rf) * ldb + k0 + kcf);
            if (n0 + rf + 32 < N)
                bfv1 = *reinterpret_cast<const float4*>(Bf + (size_t)(n0 + rf + 32) * ldb + k0 + kcf);
        } else {
            const __half* Bh = reinterpret_cast<const __half*>(B);
            cp16((uint32_t)__cvta_generic_to_shared(&Bs[buf][rh][kch]),
                 Bh + (size_t)(n0 + rh) * ldb + k0 + kch,
                 (n0 + rh < N) ? 16 : 0);
        }
    };
    auto packh = [](const float4& f) {
        __half2 h0 = __floats2half2_rn(f.x, f.y);
        __half2 h1 = __floats2half2_rn(f.z, f.w);
        uint2 u;
        u.x = *reinterpret_cast<unsigned*>(&h0);
        u.y = *reinterpret_cast<unsigned*>(&h1);
        return u;
    };
    auto commitA = [&](int buf) {
        if constexpr (is_same_t<AT, float>::v) {
            *reinterpret_cast<uint2*>(&As[buf][rf][kcf])      = packh(afv0);
            *reinterpret_cast<uint2*>(&As[buf][rf + 32][kcf]) = packh(afv1);
        }
    };
    auto commitB = [&](int buf) {
        if constexpr (is_same_t<BT, float>::v) {
            *reinterpret_cast<uint2*>(&Bs[buf][rf][kcf])      = packh(bfv0);
            *reinterpret_cast<uint2*>(&Bs[buf][rf + 32][kcf]) = packh(bfv1);
        }
    };

    fetchA(0, 0); fetchB(0, 0);
    cp_commit();
    commitA(0); commitB(0);
    cp_wait0();
    __syncthreads();

    const int fr = lane & 15;
    const int fc = (lane >> 4) << 3;

    int buf = 0;
    for (int k0 = 0; k0 < K; k0 += 32) {
        const bool hn = (k0 + 32 < K);
        if (hn) { fetchA(k0 + 32, buf ^ 1); fetchB(k0 + 32, buf ^ 1); cp_commit(); }

#pragma unroll
        for (int ks = 0; ks < 2; ++ks) {
            uint32_t a0, a1, a2, a3;
            {
                uint32_t addr = (uint32_t)__cvta_generic_to_shared(
                    &As[buf][wm * 16 + fr][ks * 16 + fc]);
                asm volatile("ldmatrix.sync.aligned.m8n8.x4.shared.b16 {%0,%1,%2,%3}, [%4];"
                             : "=r"(a0), "=r"(a1), "=r"(a2), "=r"(a3) : "r"(addr));
            }
#pragma unroll
            for (int jp = 0; jp < 2; ++jp) {
                uint32_t b0, b1, b2, b3;
                uint32_t addr = (uint32_t)__cvta_generic_to_shared(
                    &Bs[buf][wn * 32 + jp * 16 + fr][ks * 16 + fc]);
                asm volatile("ldmatrix.sync.aligned.m8n8.x4.shared.b16 {%0,%1,%2,%3}, [%4];"
                             : "=r"(b0), "=r"(b1), "=r"(b2), "=r"(b3) : "r"(addr));
                asm volatile("mma.sync.aligned.m16n8k16.row.col.f32.f16.f16.f32 "
                             "{%0,%1,%2,%3}, {%4,%5,%6,%7}, {%8,%9}, {%0,%1,%2,%3};"
                             : "+f"(acc[2 * jp][0]), "+f"(acc[2 * jp][1]),
                               "+f"(acc[2 * jp][2]), "+f"(acc[2 * jp][3])
                             : "r"(a0), "r"(a1), "r"(a2), "r"(a3), "r"(b0), "r"(b2));
                asm volatile("mma.sync.aligned.m16n8k16.row.col.f32.f16.f16.f32 "
                             "{%0,%1,%2,%3}, {%4,%5,%6,%7}, {%8,%9}, {%0,%1,%2,%3};"
                             : "+f"(acc[2 * jp + 1][0]), "+f"(acc[2 * jp + 1][1]),
                               "+f"(acc[2 * jp + 1][2]), "+f"(acc[2 * jp + 1][3])
                             : "r"(a0), "r"(a1), "r"(a2), "r"(a3), "r"(b1), "r"(b3));
            }
        }
        if (hn) { commitA(buf ^ 1); commitB(buf ^ 1); cp_wait0(); }
        __syncthreads();
        buf ^= 1;
    }

    const int er = lane >> 2;
    const int ec = (lane & 3) * 2;
#pragma unroll
    for (int j = 0; j < 4; ++j) {
        const int colb = n0 + wn * 32 + j * 8 + ec;
#pragma unroll
        for (int rr = 0; rr < 2; ++rr) {
            const int row = m0 + wm * 16 + er + rr * 8;
            if (row < M) {
#pragma unroll
                for (int cc = 0; cc < 2; ++cc) {
                    const int c = colb + cc;
                    if (c < N) {
                        float v = acc[j][rr * 2 + cc];
                        if (bias) v += bias[c];
                        if (ATOMIC) {
                            atomicAdd(reinterpret_cast<float*>(&C[(size_t)row * ldc + c]), v);
                        } else {
                            float v1 = v;
                            if (addA) v1 += addA[c];
                            C[(size_t)row * ldc + c] = st_conv(v1, (OT*)nullptr);
                            if (C2) C2[(size_t)row * ldc + c] = __float2half(v + add2[c]);
                        }
                    }
                }
            }
        }
    }
}

// ---------------- stage 1: projections + pe tables (fp8 x64) + Wr transpose + zero out ----------------
__global__ void __launch_bounds__(256) k_pre(
    const float* __restrict__ key, const float* __restrict__ query, const float* __restrict__ value,
    const float* __restrict__ Wk, const float* __restrict__ bk,
    const float* __restrict__ Wq, const float* __restrict__ bq,
    const float* __restrict__ Wv, const float* __restrict__ bv,
    const float* __restrict__ pe, const float* __restrict__ W_fus,
    const float* __restrict__ b_fus, const float* __restrict__ Wr,
    const float* __restrict__ u_bias, const float* __restrict__ v_bias,
    float* __restrict__ out)
{
    const int z = blockIdx.z;
    const int bx = blockIdx.x, by = blockIdx.y;
    if (z == 0) {
        hgemm<float, float, false, __half>(bx, by, key, H_, Wk, H_, bk, d_kh, H_, ML_, H_, H_);
    } else if (z == 1) {
        hgemm<float, float, false, __half>(bx, by, query, H_, Wq, H_, bq, d_qkAh, H_, ML_, H_, H_,
                                           u_bias, d_uh, v_bias);
    } else if (z == 2) {
        hgemm<float, float, false, __half>(bx, by, value, H_, Wv, H_, bv, d_vh, H_, ML_, H_, H_);
    } else if (z < 7) {
        const int t = z - 3;   // tables 0..3; b_fus folded into T0; stored fp8 x64
        hgemm<float, float, false, __nv_fp8_e4m3>(bx, by, pe + 321 * H_, H_, W_fus + t * 256, 2 * H_,
                                                  (t == 0) ? b_fus : nullptr,
                                                  d_T8 + (size_t)t * TROWS_ * H_, H_, TROWS_, H_, 256);
    } else {
        const int stride = 48 * 256;
        const int start = (by * 8 + bx) * 256 + threadIdx.x;
        for (int i = start; i < NH_ * H_ * 64; i += stride) {
            const int h = i >> 15;
            const int rem = i & 32767;
            const int f = rem >> 6;
            const int d = rem & 63;
            d_WrTh[i] = __float2half(Wr[(size_t)(h * 64 + d) * H_ + f]);
        }
        // zero d_out for k_ff's atomic accumulation (independent of everything)
        const float4 z4 = make_float4(0.f, 0.f, 0.f, 0.f);
        float4* o4 = reinterpret_cast<float4*>(out);
        for (int i = start; i < (ML_ * H_) / 4; i += stride) o4[i] = z4;
    }
}

// -------- stage 2: g + per-head qk GEMMs (compact grid) --------
__global__ void __launch_bounds__(256) k_gqk()
{
    const int z = blockIdx.z;
    if (z < 8) {
        hgemm<__half, __half, false, __half>(blockIdx.x, blockIdx.y,
                                             d_uh + z * 64, H_, d_WrTh + (size_t)z * H_ * 64, 64,
                                             nullptr, d_gh + z * H_, NH_ * H_, ML_, H_, 64);
    } else {
        const int t = (z - 8) * 48 + blockIdx.y * 8 + blockIdx.x;
        if (t >= 144) return;
        const int combo = t / 9, tile = t % 9;
        const int b = combo >> 3, n = combo & 7;
        hgemm<__half, __half, false, float>(tile % 3, tile / 3,
                                            d_qkAh + (size_t)b * L_ * H_ + n * 64, H_,
                                            d_kh   + (size_t)b * L_ * H_ + n * 64, H_, nullptr,
                                            d_qk + (size_t)combo * L_ * L_, L_, L_, L_, 64);
    }
}

// 16 fp8 (uint4) -> 8 half2
__device__ __forceinline__ void cvt_fp8x16(const uint4& v, __half2* out) {
    const uint32_t w[4] = {v.x, v.y, v.z, v.w};
#pragma unroll
    for (int i = 0; i < 4; ++i) {
        unsigned short lo = (unsigned short)(w[i] & 0xffffu);
        unsigned short hi = (unsigned short)(w[i] >> 16);
        uint32_t r0, r1;
        asm("cvt.rn.f16x2.e4m3x2 %0, %1;" : "=r"(r0) : "h"(lo));
        asm("cvt.rn.f16x2.e4m3x2 %0, %1;" : "=r"(r1) : "h"(hi));
        out[2 * i]     = *reinterpret_cast<__half2*>(&r0);
        out[2 * i + 1] = *reinterpret_cast<__half2*>(&r1);
    }
}

// ------ stage 3: fused rel-scores (tensor-core, fp8 tables) + softmax + attn@V ------
__global__ void __launch_bounds__(256, 3) k_attn(
    const int* __restrict__ pos_s,
    const int* __restrict__ pos_e,
    const int* __restrict__ seq_len)
{
    __shared__ __align__(16) __half g_s[NH_][GP_];
    __shared__ __align__(16) __half R[16][GP_];
    __shared__ __align__(16) float sc[NH_][SCP_];
    __shared__ int ksp[L_], kep[L_];

    const int m = blockIdx.x;          // b*L + q
    const int b = m / L_;
    const int qi = m % L_;
    const int tid = threadIdx.x;
    const int lane = tid & 31;
    const int warp = tid >> 5;

    for (int i = tid; i < (NH_ * H_) / 8; i += 256) {
        const int n = i >> 6;
        const int c = i & 63;
        *reinterpret_cast<uint4*>(&g_s[n][c * 8]) =
            *reinterpret_cast<const uint4*>(d_gh + (size_t)m * (NH_ * H_) + n * H_ + c * 8);
    }
    for (int i = tid; i < NH_ * L_; i += 256) {
        const int n = i / L_, k = i % L_;
        sc[n][k] = d_qk[((size_t)(b * NH_ + n) * L_ + qi) * L_ + k];
    }
    for (int i = tid; i < L_; i += 256) { ksp[i] = pos_s[b * L_ + i]; kep[i] = pos_e[b * L_ + i]; }
    const int psq = pos_s[m], peq = pos_e[m];
    const int slen = seq_len[b];
    __syncthreads();

    const __half2 hz = __float2half2_rn(0.f);
    const uint8_t* __restrict__ T8 = reinterpret_cast<const uint8_t*>(d_T8);
    const int lane16 = lane << 4;
    const int fr = lane & 15;
    const int fc = (lane >> 4) << 3;
    const int er = lane >> 2;
    const int ec = (lane & 3) * 2;
    const int nch = (slen + 15) >> 4;

    uint4 A0, A1, A2, A3;
    auto loadKey = [&](int kk) {
        A0 = *reinterpret_cast<const uint4*>(T8 + (size_t)((0 * TROWS_ + psq - ksp[kk] + 191) << 9) + lane16);
        A1 = *reinterpret_cast<const uint4*>(T8 + (size_t)((1 * TROWS_ + psq - kep[kk] + 191) << 9) + lane16);
        A2 = *reinterpret_cast<const uint4*>(T8 + (size_t)((2 * TROWS_ + peq - ksp[kk] + 191) << 9) + lane16);
        A3 = *reinterpret_cast<const uint4*>(T8 + (size_t)((3 * TROWS_ + peq - kep[kk] + 191) << 9) + lane16);
    };
    auto reluStore = [&](int kl) {
        __half2 t0[8], t1[8], t2[8], t3[8];
        cvt_fp8x16(A0, t0); cvt_fp8x16(A1, t1);
        cvt_fp8x16(A2, t2); cvt_fp8x16(A3, t3);
        __half2 r[8];
#pragma unroll
        for (int j = 0; j < 8; ++j) {
            __half2 s = __hadd2(__hadd2(t0[j], t1[j]), __hadd2(t2[j], t3[j]));
            r[j] = __hmax2(s, hz);
        }
        *reinterpret_cast<uint4*>(&R[kl][lane16])     = *reinterpret_cast<uint4*>(&r[0]);
        *reinterpret_cast<uint4*>(&R[kl][lane16 + 8]) = *reinterpret_cast<uint4*>(&r[4]);
    };

    const int kl0 = warp * 2;
    loadKey(kl0);
#pragma unroll 1
    for (int ch = 0; ch < nch; ++ch) {
        const int kb = ch * 16;
        reluStore(kl0);
        loadKey(kb + kl0 + 1);
        reluStore(kl0 + 1);
        if (ch + 1 < nch) loadKey(kb + 16 + kl0);
        __syncthreads();

        float acc[4] = {0.f, 0.f, 0.f, 0.f};
#pragma unroll
        for (int ks = 0; ks < 4; ++ks) {
            const int kd = (warp * 4 + ks) * 16;
            uint32_t a0, a1, a2, a3;
            uint32_t addrA = (uint32_t)__cvta_generic_to_shared(&R[fr][kd + fc]);
            asm volatile("ldmatrix.sync.aligned.m8n8.x4.shared.b16 {%0,%1,%2,%3}, [%4];"
                         : "=r"(a0), "=r"(a1), "=r"(a2), "=r"(a3) : "r"(addrA));
            uint32_t b0, b1;
            uint32_t addrB = (uint32_t)__cvta_generic_to_shared(
                &g_s[lane & 7][kd + ((lane >> 3) & 1) * 8]);
            asm volatile("ldmatrix.sync.aligned.m8n8.x2.shared.b16 {%0,%1}, [%2];"
                         : "=r"(b0), "=r"(b1) : "r"(addrB));
            asm volatile("mma.sync.aligned.m16n8k16.row.col.f32.f16.f16.f32 "
                         "{%0,%1,%2,%3}, {%4,%5,%6,%7}, {%8,%9}, {%0,%1,%2,%3};"
                         : "+f"(acc[0]), "+f"(acc[1]), "+f"(acc[2]), "+f"(acc[3])
                         : "r"(a0), "r"(a1), "r"(a2), "r"(a3), "r"(b0), "r"(b1));
        }
        const float is = 1.f / 64.f;
        atomicAdd(&sc[ec][kb + er], acc[0] * is);
        atomicAdd(&sc[ec + 1][kb + er], acc[1] * is);
        atomicAdd(&sc[ec][kb + er + 8], acc[2] * is);
        atomicAdd(&sc[ec + 1][kb + er + 8], acc[3] * is);
        __syncthreads();
    }

    // softmax over k (scale + mask fused), warp = head
    {
        const int n = warp;
        float val[6];
        float mx = -3.4e38f;
#pragma unroll
        for (int j = 0; j < 6; ++j) {
            const int k = lane + 32 * j;
            const float v = sc[n][k] * 0.125f;
            val[j] = (k < slen) ? v : -1e30f;
            mx = fmaxf(mx, val[j]);
        }
#pragma unroll
        for (int s = 16; s > 0; s >>= 1) mx = fmaxf(mx, __shfl_xor_sync(0xffffffffu, mx, s));
        float sum = 0.f;
#pragma unroll
        for (int j = 0; j < 6; ++j) {
            val[j] = __expf(val[j] - mx);
            sum += val[j];
        }
#pragma unroll
        for (int s = 16; s > 0; s >>= 1) sum += __shfl_xor_sync(0xffffffffu, sum, s);
        const float inv = 1.f / sum;
#pragma unroll
        for (int j = 0; j < 6; ++j) sc[n][lane + 32 * j] = val[j] * inv;
    }
    __syncwarp();

    // out[m, h] = sum_{k<slen} attn[n,k] * v_half[b,k,h]
    {
        const __half* __restrict__ vb = d_vh + (size_t)b * L_ * H_;
        const int h = tid * 2;
        const int n = warp;
        const int kmax = (slen + 3) & ~3;
        float oa = 0.f, ob = 0.f, oc = 0.f, od = 0.f;
        float pa = 0.f, pb = 0.f, pc = 0.f, pd = 0.f;
#pragma unroll 2
        for (int k = 0; k < kmax; k += 4) {
            const float a0 = sc[n][k],     a1 = sc[n][k + 1];
            const float a2 = sc[n][k + 2], a3 = sc[n][k + 3];
            __half2 v0 = *reinterpret_cast<const __half2*>(vb + (size_t)k * H_ + h);
            __half2 v1 = *reinterpret_cast<const __half2*>(vb + (size_t)(k + 1) * H_ + h);
            __half2 v2 = *reinterpret_cast<const __half2*>(vb + (size_t)(k + 2) * H_ + h);
            __half2 v3 = *reinterpret_cast<const __half2*>(vb + (size_t)(k + 3) * H_ + h);
            float2 f0 = __half22float2(v0);
            float2 f1 = __half22float2(v1);
            float2 f2 = __half22float2(v2);
            float2 f3 = __half22float2(v3);
            oa += a0 * f0.x; pa += a0 * f0.y;
            ob += a1 * f1.x; pb += a1 * f1.y;
            oc += a2 * f2.x; pc += a2 * f2.y;
            od += a3 * f3.x; pd += a3 * f3.y;
        }
        *reinterpret_cast<__half2*>(d_attnouth + (size_t)m * H_ + h) =
            __floats2half2_rn((oa + ob) + (oc + od), (pa + pb) + (pc + pd));
    }
}

// ---------------- stage 4: output projection, K-split x8 + atomic epilogue ----------------
__global__ void __launch_bounds__(256) k_ff(const float* __restrict__ Wff,
                                            const float* __restrict__ bff,
                                            float* __restrict__ out)
{
    const int c = blockIdx.z;
    hgemm<__half, float, true, float>(blockIdx.x, blockIdx.y,
                                      d_attnouth + c * 64, H_, Wff + c * 64, H_,
                                      (c == 0) ? bff : nullptr,
                                      out, H_, ML_, H_, 64);
}

// ---------------- launch ----------------
extern "C" void kernel_launch(void* const* d_in, const int* in_sizes, int n_in,
                              void* d_out, int out_size)
{
    (void)n_in; (void)out_size;
    const float* key     = (const float*)d_in[0];
    const float* query   = (const float*)d_in[1];
    const float* value   = (const float*)d_in[2];
    const int*   seq_len = (const int*)d_in[3];
    const int ip = (in_sizes[4] == 1) ? 5 : 4;   // skip lex_num if present
    const int*   pos_s  = (const int*)d_in[ip + 0];
    const int*   pos_e  = (const int*)d_in[ip + 1];
    const float* pe     = (const float*)d_in[ip + 2];
    const float* W_fus  = (const float*)d_in[ip + 3];
    const float* b_fus  = (const float*)d_in[ip + 4];
    const float* Wk     = (const float*)d_in[ip + 5];
    const float* bk     = (const float*)d_in[ip + 6];
    const float* Wq     = (const float*)d_in[ip + 7];
    const float* bq     = (const float*)d_in[ip + 8];
    const float* Wv     = (const float*)d_in[ip + 9];
    const float* bv     = (const float*)d_in[ip + 10];
    const float* Wr     = (const float*)d_in[ip + 11];
    const float* u_bias = (const float*)d_in[ip + 13];
    const float* v_bias = (const float*)d_in[ip + 14];
    const float* Wff    = (const float*)d_in[ip + 15];
    const float* bff    = (const float*)d_in[ip + 16];
    // d_in[ip+12] (br) intentionally unused: constant over k under softmax

    k_pre  <<<dim3(8, 6, 8), 256>>>(key, query, value, Wk, bk, Wq, bq, Wv, bv,
                                    pe, W_fus, b_fus, Wr, u_bias, v_bias, (float*)d_out);
    k_gqk  <<<dim3(8, 6, 11), 256>>>();
    k_attn <<<ML_, 256>>>(pos_s, pos_e, seq_len);
    k_ff   <<<dim3(8, 6, 8), 256>>>(Wff, bff, (float*)d_out);
}